// round 7
// baseline (speedup 1.0000x reference)
#include <cuda_runtime.h>
#include <cuda_bf16.h>
#include <cstdint>

// Problem constants
#define BB 4
#define SS 1024
#define DD 1024
#define HH 16
#define DH 64
#define LL 12
#define VV 32000
#define NTOK (BB*SS)        // 4096 tokens

// ---------------- scratch (static device globals; no allocs allowed) ----------
__device__ float g_x[NTOK * DD];                          // running activations fp32
__device__ __nv_bfloat16 g_hh[NTOK * DD], g_hl[NTOK * DD];    // post-LN1 hi/lo
__device__ __nv_bfloat16 g_th[NTOK * DD], g_tl[NTOK * DD];    // post-LN2 hi/lo
__device__ __nv_bfloat16 g_ah[NTOK * DD], g_al[NTOK * DD];    // attn out hi/lo
__device__ __nv_bfloat16 g_xh[NTOK * DD], g_xl[NTOK * DD];    // final x hi/lo
__device__ __nv_bfloat16 g_qkvh[NTOK * 3 * DD];
__device__ __nv_bfloat16 g_qkvl[NTOK * 3 * DD];

// bf16 hi/lo split weights, all in [N,K] layout
#define WA_T_OFF  0
#define WP_T_OFF  (12*3072*1024)
#define WF_T_OFF  (WP_T_OFF + 12*1024*1024)
#define WOUT_OFF  (WF_T_OFF + 12*1024*1024)
#define W_T_TOTAL (WOUT_OFF + VV*1024)
__device__ __nv_bfloat16 g_wh[W_T_TOTAL];
__device__ __nv_bfloat16 g_wl[W_T_TOTAL];

// ============================ helpers ==========================================
__device__ __forceinline__ uint32_t smem_u32(const void* p) {
    uint32_t a;
    asm("{ .reg .u64 t; cvta.to.shared.u64 t, %1; cvt.u32.u64 %0, t; }" : "=r"(a) : "l"(p));
    return a;
}
__device__ __forceinline__ uint32_t sw128(uint32_t o) { return o ^ ((o >> 3) & 0x70); }

__device__ __forceinline__ void cp16(uint32_t dst, const void* src) {
    asm volatile("cp.async.cg.shared.global [%0], [%1], 16;" :: "r"(dst), "l"(src) : "memory");
}
#define CP_COMMIT() asm volatile("cp.async.commit_group;" ::: "memory")
#define CP_WAIT0()  asm volatile("cp.async.wait_group 0;" ::: "memory")
#define CP_WAIT1()  asm volatile("cp.async.wait_group 1;" ::: "memory")

__device__ __forceinline__ void ldsm_x4(uint32_t* r, uint32_t addr) {
    asm volatile("ldmatrix.sync.aligned.m8n8.x4.shared.b16 {%0,%1,%2,%3}, [%4];"
        : "=r"(r[0]), "=r"(r[1]), "=r"(r[2]), "=r"(r[3]) : "r"(addr));
}
__device__ __forceinline__ void ldsm_x4_t(uint32_t* r, uint32_t addr) {
    asm volatile("ldmatrix.sync.aligned.m8n8.x4.trans.shared.b16 {%0,%1,%2,%3}, [%4];"
        : "=r"(r[0]), "=r"(r[1]), "=r"(r[2]), "=r"(r[3]) : "r"(addr));
}
__device__ __forceinline__ void mma_bf16(float* d, const uint32_t* a, const uint32_t* b) {
    asm volatile(
        "mma.sync.aligned.m16n8k16.row.col.f32.bf16.bf16.f32 "
        "{%0,%1,%2,%3}, {%4,%5,%6,%7}, {%8,%9}, {%0,%1,%2,%3};"
        : "+f"(d[0]), "+f"(d[1]), "+f"(d[2]), "+f"(d[3])
        : "r"(a[0]), "r"(a[1]), "r"(a[2]), "r"(a[3]), "r"(b[0]), "r"(b[1]));
}

__device__ __forceinline__ uint32_t pack_bf2(__nv_bfloat16 a, __nv_bfloat16 b) {
    return (uint32_t)__bfloat16_as_ushort(a) | ((uint32_t)__bfloat16_as_ushort(b) << 16);
}
__device__ __forceinline__ void split2(float x, float y, uint32_t& hi, uint32_t& lo) {
    __nv_bfloat16 hx = __float2bfloat16(x), hy = __float2bfloat16(y);
    hi = pack_bf2(hx, hy);
    lo = pack_bf2(__float2bfloat16(x - __bfloat162float(hx)),
                  __float2bfloat16(y - __bfloat162float(hy)));
}
__device__ __forceinline__ void split4(float4 v, uint32_t& h01, uint32_t& h23,
                                       uint32_t& l01, uint32_t& l23) {
    split2(v.x, v.y, h01, l01);
    split2(v.z, v.w, h23, l23);
}
__device__ __forceinline__ float bf2sum(uint32_t hi, uint32_t lo, int idx) {
    __nv_bfloat16 h = __ushort_as_bfloat16((unsigned short)(idx ? (hi >> 16) : (hi & 0xFFFF)));
    __nv_bfloat16 l = __ushort_as_bfloat16((unsigned short)(idx ? (lo >> 16) : (lo & 0xFFFF)));
    return __bfloat162float(h) + __bfloat162float(l);
}

// ============================ embedding / LN ===================================
__global__ void embed_kernel(const int* __restrict__ X, const float* __restrict__ emb,
                             const float* __restrict__ pe, float* __restrict__ x)
{
    int m = blockIdx.x;
    int t = threadIdx.x;
    int tok = X[m];
    int b = m >> 10;
    float4 e = ((const float4*)(emb + (size_t)tok * DD))[t];
    float4 p = ((const float4*)(pe  + (size_t)b   * DD))[t];
    float4 o;
    o.x = e.x * 32.0f + p.x;  o.y = e.y * 32.0f + p.y;
    o.z = e.z * 32.0f + p.z;  o.w = e.w * 32.0f + p.w;
    ((float4*)(x + (size_t)m * DD))[t] = o;
}

__global__ void ln_split_kernel(const float* __restrict__ x, const float* __restrict__ g,
                                const float* __restrict__ b,
                                __nv_bfloat16* __restrict__ Yh,
                                __nv_bfloat16* __restrict__ Yl)
{
    int row = blockIdx.x;
    int t = threadIdx.x;
    float4 v = ((const float4*)(x + (size_t)row * DD))[t];
    float s  = v.x + v.y + v.z + v.w;
    float ss = v.x*v.x + v.y*v.y + v.z*v.z + v.w*v.w;
    #pragma unroll
    for (int o = 16; o; o >>= 1) {
        s  += __shfl_xor_sync(0xFFFFFFFFu, s,  o);
        ss += __shfl_xor_sync(0xFFFFFFFFu, ss, o);
    }
    __shared__ float sm[16];
    __shared__ float s_mu, s_r;
    int w = t >> 5;
    if ((t & 31) == 0) { sm[w] = s; sm[8 + w] = ss; }
    __syncthreads();
    if (t == 0) {
        float a = 0.f, c = 0.f;
        #pragma unroll
        for (int i = 0; i < 8; i++) { a += sm[i]; c += sm[8 + i]; }
        float mu  = a * (1.0f / DD);
        float var = c * (1.0f / DD) - mu * mu;
        s_mu = mu;
        s_r  = rsqrtf(var + 1e-5f);
    }
    __syncthreads();
    float mu = s_mu, r = s_r;
    float4 gv = ((const float4*)g)[t];
    float4 bv = ((const float4*)b)[t];
    float4 o;
    o.x = (v.x - mu) * r * gv.x + bv.x;
    o.y = (v.y - mu) * r * gv.y + bv.y;
    o.z = (v.z - mu) * r * gv.z + bv.z;
    o.w = (v.w - mu) * r * gv.w + bv.w;
    uint32_t h01, h23, l01, l23;
    split4(o, h01, h23, l01, l23);
    ((uint2*)(Yh + (size_t)row * DD))[t] = make_uint2(h01, h23);
    ((uint2*)(Yl + (size_t)row * DD))[t] = make_uint2(l01, l23);
}

// ================== weight prep ===============================================
__global__ void transpose_split_kernel(const float* __restrict__ W,
                                       __nv_bfloat16* __restrict__ Wh,
                                       __nv_bfloat16* __restrict__ Wl,
                                       int K, int N)
{
    __shared__ float t[32][33];
    int l = blockIdx.z;
    W  += (size_t)l * K * N;
    Wh += (size_t)l * N * K;
    Wl += (size_t)l * N * K;
    int n0 = blockIdx.x * 32, k0 = blockIdx.y * 32;
    int tx = threadIdx.x, ty = threadIdx.y;
    #pragma unroll
    for (int i = 0; i < 4; i++)
        t[ty + 8*i][tx] = W[(size_t)(k0 + ty + 8*i) * N + n0 + tx];
    __syncthreads();
    #pragma unroll
    for (int i = 0; i < 4; i++) {
        float v = t[tx][ty + 8*i];
        __nv_bfloat16 h = __float2bfloat16(v);
        __nv_bfloat16 lo = __float2bfloat16(v - __bfloat162float(h));
        size_t oi = (size_t)(n0 + ty + 8*i) * K + k0 + tx;
        Wh[oi] = h; Wl[oi] = lo;
    }
}

__global__ void split_kernel(const float* __restrict__ W,
                             __nv_bfloat16* __restrict__ Wh,
                             __nv_bfloat16* __restrict__ Wl)
{
    size_t i = (size_t)blockIdx.x * blockDim.x + threadIdx.x;
    float4 v = ((const float4*)W)[i];
    uint32_t h01, h23, l01, l23;
    split4(v, h01, h23, l01, l23);
    ((uint2*)Wh)[i] = make_uint2(h01, h23);
    ((uint2*)Wl)[i] = make_uint2(l01, l23);
}

// ====================== HMMA bf16x3 GEMM: 256x128 CTA tile =====================
// C[M,N] = (Ah+Al)[M,K] @ (Bh+Bl)^T[N,K], fp32 accum, 3-term product.
// 256 threads = 8 warps (4M x 2N), warp tile 64x64. 2-stage cp.async pipeline.
#define A_HI 0
#define A_LO 32768
#define B_HI 65536
#define B_LO 81920
#define STAGE_BYTES 98304
#define GEMM_DSMEM (2*STAGE_BYTES + 1024)

template<int RESMODE, bool OUTS>
__global__ void __launch_bounds__(256, 1)
gemm_bb(const __nv_bfloat16* __restrict__ Ah, const __nv_bfloat16* __restrict__ Al,
        const __nv_bfloat16* __restrict__ Bh, const __nv_bfloat16* __restrict__ Bl,
        const float* __restrict__ bias,
        const float* __restrict__ resf,
        const __nv_bfloat16* __restrict__ resh, const __nv_bfloat16* __restrict__ resl,
        float* __restrict__ C,
        __nv_bfloat16* __restrict__ Ch, __nv_bfloat16* __restrict__ Cl,
        int M, int N, int K)
{
    extern __shared__ char dsm[];
    uint32_t raw = smem_u32(dsm);
    uint32_t tb = (raw + 1023u) & ~1023u;

    const int tid = threadIdx.x;
    const int l   = tid & 31;
    const int wid = tid >> 5;
    const int wm  = (wid & 3) * 64;       // 4 M-warps
    const int wn  = (wid >> 2) * 64;      // 2 N-warps
    const int bm  = blockIdx.x * 256;
    const int bn  = blockIdx.y * 128;

    const uint32_t hi16 = (uint32_t)((l >> 4) * 16);
    uint32_t abase[4], amask[4], bbase[4], bmask[4];
    #pragma unroll
    for (int mi = 0; mi < 4; mi++) {
        uint32_t r = (uint32_t)(wm + mi * 16 + (l & 15));
        abase[mi] = r * 128;
        amask[mi] = (r & 7) << 4;
    }
    #pragma unroll
    for (int nb = 0; nb < 4; nb++) {
        uint32_t r = (uint32_t)(wn + nb * 16 + (l & 15));
        bbase[nb] = r * 128;
        bmask[nb] = (r & 7) << 4;
    }

    float d[4][8][4];
    #pragma unroll
    for (int i = 0; i < 4; i++)
        #pragma unroll
        for (int j = 0; j < 8; j++)
            #pragma unroll
            for (int k = 0; k < 4; k++) d[i][j][k] = 0.f;

    const int nt = K >> 6;

    // stage: A 256x64 hi/lo (64KB) + B 128x64 hi/lo (32KB)
    #define LOAD_T(stg, k0) { \
        uint32_t base = tb + (stg) * STAGE_BYTES; \
        _Pragma("unroll") \
        for (int i = 0; i < 8; i++) { \
            int c = tid + i * 256; int r = c >> 3, s = c & 7; \
            uint32_t off = sw128((uint32_t)(r * 128 + s * 16)); \
            size_t ga = (size_t)(bm + r) * K + (k0) + s * 8; \
            cp16(base + A_HI + off, Ah + ga); \
            cp16(base + A_LO + off, Al + ga); } \
        _Pragma("unroll") \
        for (int i = 0; i < 4; i++) { \
            int c = tid + i * 256; int r = c >> 3, s = c & 7; \
            uint32_t off = sw128((uint32_t)(r * 128 + s * 16)); \
            size_t gb = (size_t)(bn + r) * K + (k0) + s * 8; \
            cp16(base + B_HI + off, Bh + gb); \
            cp16(base + B_LO + off, Bl + gb); } }

    LOAD_T(0, 0); CP_COMMIT();
    LOAD_T(1, 64); CP_COMMIT();

    for (int t = 0; t < nt; t++) {
        if (t + 1 < nt) { CP_WAIT1(); } else { CP_WAIT0(); }
        __syncthreads();
        {
            uint32_t sb = tb + (uint32_t)(t & 1) * STAGE_BYTES;
            #pragma unroll
            for (int ks = 0; ks < 4; ks++) {
                const uint32_t ko = (uint32_t)(ks * 32);
                uint32_t aH[4][4], aL[4][4];
                #pragma unroll
                for (int mi = 0; mi < 4; mi++) {
                    uint32_t ao = abase[mi] + ((hi16 + ko) ^ amask[mi]);
                    ldsm_x4(aH[mi], sb + A_HI + ao);
                    ldsm_x4(aL[mi], sb + A_LO + ao);
                }
                uint32_t bH[8][2], bL[8][2];
                #pragma unroll
                for (int nb = 0; nb < 4; nb++) {
                    uint32_t bo = bbase[nb] + ((hi16 + ko) ^ bmask[nb]);
                    uint32_t r4[4];
                    ldsm_x4(r4, sb + B_HI + bo);
                    bH[2*nb][0] = r4[0]; bH[2*nb][1] = r4[2];
                    bH[2*nb+1][0] = r4[1]; bH[2*nb+1][1] = r4[3];
                    ldsm_x4(r4, sb + B_LO + bo);
                    bL[2*nb][0] = r4[0]; bL[2*nb][1] = r4[2];
                    bL[2*nb+1][0] = r4[1]; bL[2*nb+1][1] = r4[3];
                }
                #pragma unroll
                for (int nj = 0; nj < 8; nj++) {
                    #pragma unroll
                    for (int mi = 0; mi < 4; mi++) {
                        mma_bf16(d[mi][nj], aH[mi], bH[nj]);
                        mma_bf16(d[mi][nj], aH[mi], bL[nj]);
                        mma_bf16(d[mi][nj], aL[mi], bH[nj]);
                    }
                }
            }
        }
        __syncthreads();
        if (t + 2 < nt) {
            LOAD_T(t & 1, (t + 2) << 6);
            CP_COMMIT();
        }
    }

    // ---- epilogue ----
    #pragma unroll
    for (int mi = 0; mi < 4; mi++) {
        #pragma unroll
        for (int half = 0; half < 2; half++) {
            int row = bm + wm + mi * 16 + half * 8 + (l >> 2);
            #pragma unroll
            for (int nj = 0; nj < 8; nj++) {
                int col = bn + wn + nj * 8 + 2 * (l & 3);
                float v0 = d[mi][nj][2 * half];
                float v1 = d[mi][nj][2 * half + 1];
                if (bias) { v0 += bias[col]; v1 += bias[col + 1]; }
                size_t ri = (size_t)row * N + col;
                if (RESMODE == 1) {
                    float2 r2 = *(const float2*)&resf[ri];
                    v0 += r2.x; v1 += r2.y;
                } else if (RESMODE == 2) {
                    uint32_t rh = *(const uint32_t*)&resh[ri];
                    uint32_t rl = *(const uint32_t*)&resl[ri];
                    v0 += bf2sum(rh, rl, 0);
                    v1 += bf2sum(rh, rl, 1);
                }
                if (OUTS) {
                    uint32_t hi, lo;
                    split2(v0, v1, hi, lo);
                    *(uint32_t*)&Ch[ri] = hi;
                    *(uint32_t*)&Cl[ri] = lo;
                } else {
                    float2 o; o.x = v0; o.y = v1;
                    *(float2*)&C[ri] = o;
                }
            }
        }
    }
}

// ================== HMMA flash attention (bf16x3) ==============================
#define AQ_HI 0
#define AQ_LO 16384
#define AKV_OFF 32768
#define AKV_BUF 32768
#define ATTN_DSMEM (AKV_OFF + 2*AKV_BUF + 1024)

__global__ void __launch_bounds__(256, 1)
attn_mma(const __nv_bfloat16* __restrict__ qh, const __nv_bfloat16* __restrict__ ql,
         __nv_bfloat16* __restrict__ oh, __nv_bfloat16* __restrict__ ol)
{
    extern __shared__ char dsm[];
    uint32_t raw = smem_u32(dsm);
    uint32_t tb = (raw + 1023u) & ~1023u;

    const int tid = threadIdx.x;
    const int l   = tid & 31;
    const int w   = tid >> 5;
    const int bh  = blockIdx.y;
    const int b   = bh >> 4;
    const int h   = bh & 15;
    const int q0  = blockIdx.x * 128;
    const size_t hoff = (size_t)h * DH;

    #pragma unroll
    for (int i = 0; i < 8; i++) {
        int lin = tid + i * 256;
        int reg = lin >> 10, row = (lin >> 3) & 127, ch = lin & 7;
        const __nv_bfloat16* src = (reg ? ql : qh)
            + (size_t)(b * SS + q0 + row) * (3 * DD) + hoff + ch * 8;
        cp16(tb + (reg ? AQ_LO : AQ_HI) + sw128((uint32_t)(row * 128 + ch * 16)), src);
    }
    #define LOAD_KV(t, buf) { \
        _Pragma("unroll") \
        for (int i = 0; i < 8; i++) { \
            int lin = tid + i * 256; \
            int kv = lin >> 10, reg = (lin >> 9) & 1, row = (lin >> 3) & 63, ch = lin & 7; \
            const __nv_bfloat16* src = (reg ? ql : qh) \
                + (size_t)(b * SS + (t) * 64 + row) * (3 * DD) \
                + (kv ? 2 * DD : DD) + hoff + ch * 8; \
            cp16(tb + AKV_OFF + (buf) * AKV_BUF + kv * 16384 + reg * 8192 \
                 + sw128((uint32_t)(row * 128 + ch * 16)), src); } }

    LOAD_KV(0, 0); CP_COMMIT();
    LOAD_KV(1, 1); CP_COMMIT();

    float od[8][4];
    #pragma unroll
    for (int j = 0; j < 8; j++)
        #pragma unroll
        for (int k = 0; k < 4; k++) od[j][k] = 0.f;
    float m0 = -1e30f, m1 = -1e30f, l0 = 0.f, l1 = 0.f;

    uint32_t aQh[4][4], aQl[4][4];
    const uint32_t qrow = (uint32_t)(w * 16 + (l & 15));
    const uint32_t qmask = (qrow & 7) << 4;
    const uint32_t hi16 = (uint32_t)((l >> 4) * 16);

    for (int t = 0; t < 16; t++) {
        const int buf = t & 1;
        if (t < 15) { CP_WAIT1(); } else { CP_WAIT0(); }
        __syncthreads();
        if (t == 0) {
            #pragma unroll
            for (int ks = 0; ks < 4; ks++) {
                uint32_t off = qrow * 128 + ((hi16 + ks * 32) ^ qmask);
                ldsm_x4(aQh[ks], tb + AQ_HI + off);
                ldsm_x4(aQl[ks], tb + AQ_LO + off);
            }
        }
        const uint32_t sK = tb + AKV_OFF + buf * AKV_BUF;
        const uint32_t sKl = sK + 8192;
        const uint32_t sV = sK + 16384;
        const uint32_t sVl = sK + 24576;

        float sc[8][4];
        #pragma unroll
        for (int j = 0; j < 8; j++)
            #pragma unroll
            for (int k = 0; k < 4; k++) sc[j][k] = 0.f;
        #pragma unroll
        for (int ks = 0; ks < 4; ks++) {
            uint32_t bKh[8][2], bKl[8][2];
            #pragma unroll
            for (int nb = 0; nb < 4; nb++) {
                uint32_t row = (uint32_t)(nb * 16 + (l & 15));
                uint32_t off = row * 128 + ((hi16 + ks * 32) ^ ((row & 7) << 4));
                uint32_t r4[4];
                ldsm_x4(r4, sK + off);
                bKh[2*nb][0] = r4[0]; bKh[2*nb][1] = r4[2];
                bKh[2*nb+1][0] = r4[1]; bKh[2*nb+1][1] = r4[3];
                ldsm_x4(r4, sKl + off);
                bKl[2*nb][0] = r4[0]; bKl[2*nb][1] = r4[2];
                bKl[2*nb+1][0] = r4[1]; bKl[2*nb+1][1] = r4[3];
            }
            #pragma unroll
            for (int nj = 0; nj < 8; nj++) {
                mma_bf16(sc[nj], aQh[ks], bKh[nj]);
                mma_bf16(sc[nj], aQh[ks], bKl[nj]);
                mma_bf16(sc[nj], aQl[ks], bKh[nj]);
            }
        }

        float nm0 = m0, nm1 = m1;
        #pragma unroll
        for (int nj = 0; nj < 8; nj++) {
            nm0 = fmaxf(nm0, fmaxf(sc[nj][0], sc[nj][1]));
            nm1 = fmaxf(nm1, fmaxf(sc[nj][2], sc[nj][3]));
        }
        nm0 = fmaxf(nm0, __shfl_xor_sync(0xFFFFFFFFu, nm0, 1));
        nm0 = fmaxf(nm0, __shfl_xor_sync(0xFFFFFFFFu, nm0, 2));
        nm1 = fmaxf(nm1, __shfl_xor_sync(0xFFFFFFFFu, nm1, 1));
        nm1 = fmaxf(nm1, __shfl_xor_sync(0xFFFFFFFFu, nm1, 2));
        float cor0 = __expf(m0 - nm0), cor1 = __expf(m1 - nm1);
        m0 = nm0; m1 = nm1;
        float rs0 = 0.f, rs1 = 0.f;
        #pragma unroll
        for (int nj = 0; nj < 8; nj++) {
            sc[nj][0] = __expf(sc[nj][0] - nm0);
            sc[nj][1] = __expf(sc[nj][1] - nm0);
            sc[nj][2] = __expf(sc[nj][2] - nm1);
            sc[nj][3] = __expf(sc[nj][3] - nm1);
            rs0 += sc[nj][0] + sc[nj][1];
            rs1 += sc[nj][2] + sc[nj][3];
        }
        rs0 += __shfl_xor_sync(0xFFFFFFFFu, rs0, 1);
        rs0 += __shfl_xor_sync(0xFFFFFFFFu, rs0, 2);
        rs1 += __shfl_xor_sync(0xFFFFFFFFu, rs1, 1);
        rs1 += __shfl_xor_sync(0xFFFFFFFFu, rs1, 2);
        l0 = l0 * cor0 + rs0;
        l1 = l1 * cor1 + rs1;
        #pragma unroll
        for (int nj = 0; nj < 8; nj++) {
            od[nj][0] *= cor0; od[nj][1] *= cor0;
            od[nj][2] *= cor1; od[nj][3] *= cor1;
        }

        #pragma unroll
        for (int kj = 0; kj < 4; kj++) {
            uint32_t aPh[4], aPl[4];
            split2(sc[2*kj][0],   sc[2*kj][1],   aPh[0], aPl[0]);
            split2(sc[2*kj][2],   sc[2*kj][3],   aPh[1], aPl[1]);
            split2(sc[2*kj+1][0], sc[2*kj+1][1], aPh[2], aPl[2]);
            split2(sc[2*kj+1][2], sc[2*kj+1][3], aPh[3], aPl[3]);
            const uint32_t mat = (uint32_t)(l >> 3);
            const uint32_t vrow = (uint32_t)(kj * 16 + (mat & 1) * 8 + (l & 7));
            const uint32_t vmask = (vrow & 7) << 4;
            #pragma unroll
            for (int pp = 0; pp < 4; pp++) {
                uint32_t off = vrow * 128 + (((uint32_t)(pp * 32) + (mat >> 1) * 16) ^ vmask);
                uint32_t rh[4], rl[4];
                ldsm_x4_t(rh, sV + off);
                ldsm_x4_t(rl, sVl + off);
                uint32_t b0h[2] = {rh[0], rh[1]}, b1h[2] = {rh[2], rh[3]};
                uint32_t b0l[2] = {rl[0], rl[1]}, b1l[2] = {rl[2], rl[3]};
                mma_bf16(od[2*pp],   aPh, b0h);
                mma_bf16(od[2*pp],   aPh, b0l);
                mma_bf16(od[2*pp],   aPl, b0h);
                mma_bf16(od[2*pp+1], aPh, b1h);
                mma_bf16(od[2*pp+1], aPh, b1l);
                mma_bf16(od[2*pp+1], aPl, b1h);
            }
        }

        __syncthreads();
        if (t + 2 < 16) { LOAD_KV(t + 2, buf); CP_COMMIT(); }
    }

    float inv0 = 1.0f / l0, inv1 = 1.0f / l1;
    int row0 = q0 + w * 16 + (l >> 2);
    #pragma unroll
    for (int nj = 0; nj < 8; nj++) {
        int col = (int)hoff + nj * 8 + 2 * (l & 3);
        uint32_t hi, lo;
        split2(od[nj][0] * inv0, od[nj][1] * inv0, hi, lo);
        size_t ri0 = (size_t)(b * SS + row0) * DD + col;
        *(uint32_t*)&oh[ri0] = hi;
        *(uint32_t*)&ol[ri0] = lo;
        split2(od[nj][2] * inv1, od[nj][3] * inv1, hi, lo);
        size_t ri1 = (size_t)(b * SS + row0 + 8) * DD + col;
        *(uint32_t*)&oh[ri1] = hi;
        *(uint32_t*)&ol[ri1] = lo;
    }
}

// ---------------- launch -------------------------------------------------------
extern "C" void kernel_launch(void* const* d_in, const int* in_sizes, int n_in,
                              void* d_out, int out_size)
{
    const int*   X     = (const int*)  d_in[0];
    const float* emb   = (const float*)d_in[1];
    const float* pe    = (const float*)d_in[2];
    const float* ln1_g = (const float*)d_in[3];
    const float* ln1_b = (const float*)d_in[4];
    const float* wa    = (const float*)d_in[5];
    const float* ba    = (const float*)d_in[6];
    const float* wp    = (const float*)d_in[7];
    const float* bp    = (const float*)d_in[8];
    const float* ln2_g = (const float*)d_in[9];
    const float* ln2_b = (const float*)d_in[10];
    const float* wf    = (const float*)d_in[11];
    const float* bf    = (const float*)d_in[12];
    const float* wout  = (const float*)d_in[13];
    float* logits = (float*)d_out;

    float *x;
    __nv_bfloat16 *wh, *wl, *qkvh, *qkvl, *hh, *hl, *th, *tl, *ah, *al, *xh, *xl;
    cudaGetSymbolAddress((void**)&x,    g_x);
    cudaGetSymbolAddress((void**)&wh,   g_wh);
    cudaGetSymbolAddress((void**)&wl,   g_wl);
    cudaGetSymbolAddress((void**)&qkvh, g_qkvh);
    cudaGetSymbolAddress((void**)&qkvl, g_qkvl);
    cudaGetSymbolAddress((void**)&hh,   g_hh);
    cudaGetSymbolAddress((void**)&hl,   g_hl);
    cudaGetSymbolAddress((void**)&th,   g_th);
    cudaGetSymbolAddress((void**)&tl,   g_tl);
    cudaGetSymbolAddress((void**)&ah,   g_ah);
    cudaGetSymbolAddress((void**)&al,   g_al);
    cudaGetSymbolAddress((void**)&xh,   g_xh);
    cudaGetSymbolAddress((void**)&xl,   g_xl);

    cudaFuncSetAttribute(gemm_bb<0,true>,  cudaFuncAttributeMaxDynamicSharedMemorySize, GEMM_DSMEM);
    cudaFuncSetAttribute(gemm_bb<2,false>, cudaFuncAttributeMaxDynamicSharedMemorySize, GEMM_DSMEM);
    cudaFuncSetAttribute(gemm_bb<1,false>, cudaFuncAttributeMaxDynamicSharedMemorySize, GEMM_DSMEM);
    cudaFuncSetAttribute(gemm_bb<0,false>, cudaFuncAttributeMaxDynamicSharedMemorySize, GEMM_DSMEM);
    cudaFuncSetAttribute(attn_mma, cudaFuncAttributeMaxDynamicSharedMemorySize, ATTN_DSMEM);

    // weight prep (per replay, HBM-stream bound)
    transpose_split_kernel<<<dim3(3*DD/32, DD/32, LL), dim3(32,8)>>>(
        wa, wh + WA_T_OFF, wl + WA_T_OFF, DD, 3*DD);
    transpose_split_kernel<<<dim3(DD/32, DD/32, LL), dim3(32,8)>>>(
        wp, wh + WP_T_OFF, wl + WP_T_OFF, DD, DD);
    transpose_split_kernel<<<dim3(DD/32, DD/32, LL), dim3(32,8)>>>(
        wf, wh + WF_T_OFF, wl + WF_T_OFF, DD, DD);
    split_kernel<<<(VV*1024/4)/256, 256>>>(wout, wh + WOUT_OFF, wl + WOUT_OFF);

    embed_kernel<<<NTOK, 256>>>(X, emb, pe, x);

    for (int i = 0; i < LL; i++) {
        const float* ba_i = ba + (size_t)i * 3 * DD;
        const float* bp_i = bp + (size_t)i * DD;
        const float* bf_i = bf + (size_t)i * DD;
        const __nv_bfloat16* wa_h = wh + WA_T_OFF + (size_t)i * 3*DD * DD;
        const __nv_bfloat16* wa_l = wl + WA_T_OFF + (size_t)i * 3*DD * DD;
        const __nv_bfloat16* wp_h = wh + WP_T_OFF + (size_t)i * DD * DD;
        const __nv_bfloat16* wp_l = wl + WP_T_OFF + (size_t)i * DD * DD;
        const __nv_bfloat16* wf_h = wh + WF_T_OFF + (size_t)i * DD * DD;
        const __nv_bfloat16* wf_l = wl + WF_T_OFF + (size_t)i * DD * DD;

        ln_split_kernel<<<NTOK, 256>>>(x, ln1_g + (size_t)i * DD, ln1_b + (size_t)i * DD, hh, hl);
        gemm_bb<0,true><<<dim3(NTOK/256, 3*DD/128), 256, GEMM_DSMEM>>>(
            hh, hl, wa_h, wa_l, ba_i, nullptr, nullptr, nullptr,
            nullptr, qkvh, qkvl, NTOK, 3*DD, DD);
        attn_mma<<<dim3(SS/128, BB*HH), 256, ATTN_DSMEM>>>(qkvh, qkvl, ah, al);
        gemm_bb<2,false><<<dim3(NTOK/256, DD/128), 256, GEMM_DSMEM>>>(
            ah, al, wp_h, wp_l, bp_i, nullptr, hh, hl,
            x, nullptr, nullptr, NTOK, DD, DD);
        ln_split_kernel<<<NTOK, 256>>>(x, ln2_g + (size_t)i * DD, ln2_b + (size_t)i * DD, th, tl);
        gemm_bb<1,false><<<dim3(NTOK/256, DD/128), 256, GEMM_DSMEM>>>(
            th, tl, wf_h, wf_l, bf_i, x, nullptr, nullptr,
            x, nullptr, nullptr, NTOK, DD, DD);
    }

    split_kernel<<<(NTOK*DD/4)/256, 256>>>(x, xh, xl);
    gemm_bb<0,false><<<dim3(NTOK/256, VV/128), 256, GEMM_DSMEM>>>(
        xh, xl, wh + WOUT_OFF, wl + WOUT_OFF, nullptr, nullptr, nullptr, nullptr,
        logits, nullptr, nullptr, NTOK, VV, DD);
    (void)in_sizes; (void)n_in; (void)out_size;
}

// round 8
// speedup vs baseline: 1.4242x; 1.4242x over previous
#include <cuda_runtime.h>
#include <cuda_fp16.h>
#include <cstdint>

// Problem constants
#define BB 4
#define SS 1024
#define DD 1024
#define HH 16
#define DH 64
#define LL 12
#define VV 32000
#define NTOK (BB*SS)        // 4096 tokens

// ---------------- scratch (static device globals; no allocs allowed) ----------
__device__ float g_x[NTOK * DD];                       // running activations fp32
__device__ __half g_hh[NTOK * DD], g_hl[NTOK * DD];    // post-LN1 hi/lo (residual needs pair)
__device__ __half g_th[NTOK * DD];                     // post-LN2 hi only
__device__ __half g_ah[NTOK * DD];                     // attn out hi only
__device__ __half g_xh[NTOK * DD];                     // final x hi only
__device__ __half g_qkvh[NTOK * 3 * DD];               // qkv hi (Q uses hi; K/V use pair)
__device__ __half g_qkvl[NTOK * 3 * DD];               // qkv lo

// fp16 hi/lo split weights, all in [N,K] layout
#define WA_T_OFF  0
#define WP_T_OFF  (12*3072*1024)
#define WF_T_OFF  (WP_T_OFF + 12*1024*1024)
#define WOUT_OFF  (WF_T_OFF + 12*1024*1024)
#define W_T_TOTAL (WOUT_OFF + VV*1024)
__device__ __half g_wh[W_T_TOTAL];
__device__ __half g_wl[W_T_TOTAL];

// ============================ helpers ==========================================
__device__ __forceinline__ uint32_t smem_u32(const void* p) {
    uint32_t a;
    asm("{ .reg .u64 t; cvta.to.shared.u64 t, %1; cvt.u32.u64 %0, t; }" : "=r"(a) : "l"(p));
    return a;
}
__device__ __forceinline__ uint32_t sw128(uint32_t o) { return o ^ ((o >> 3) & 0x70); }

__device__ __forceinline__ void cp16(uint32_t dst, const void* src) {
    asm volatile("cp.async.cg.shared.global [%0], [%1], 16;" :: "r"(dst), "l"(src) : "memory");
}
#define CP_COMMIT() asm volatile("cp.async.commit_group;" ::: "memory")
#define CP_WAIT0()  asm volatile("cp.async.wait_group 0;" ::: "memory")
#define CP_WAIT1()  asm volatile("cp.async.wait_group 1;" ::: "memory")

__device__ __forceinline__ void ldsm_x4(uint32_t* r, uint32_t addr) {
    asm volatile("ldmatrix.sync.aligned.m8n8.x4.shared.b16 {%0,%1,%2,%3}, [%4];"
        : "=r"(r[0]), "=r"(r[1]), "=r"(r[2]), "=r"(r[3]) : "r"(addr));
}
__device__ __forceinline__ void ldsm_x4_t(uint32_t* r, uint32_t addr) {
    asm volatile("ldmatrix.sync.aligned.m8n8.x4.trans.shared.b16 {%0,%1,%2,%3}, [%4];"
        : "=r"(r[0]), "=r"(r[1]), "=r"(r[2]), "=r"(r[3]) : "r"(addr));
}
__device__ __forceinline__ void mma_f16(float* d, const uint32_t* a, const uint32_t* b) {
    asm volatile(
        "mma.sync.aligned.m16n8k16.row.col.f32.f16.f16.f32 "
        "{%0,%1,%2,%3}, {%4,%5,%6,%7}, {%8,%9}, {%0,%1,%2,%3};"
        : "+f"(d[0]), "+f"(d[1]), "+f"(d[2]), "+f"(d[3])
        : "r"(a[0]), "r"(a[1]), "r"(a[2]), "r"(a[3]), "r"(b[0]), "r"(b[1]));
}

__device__ __forceinline__ uint32_t packh2(__half a, __half b) {
    __half2 h = __halves2half2(a, b);
    return *(uint32_t*)&h;
}
__device__ __forceinline__ void split2h(float x, float y, uint32_t& hi, uint32_t& lo) {
    __half hx = __float2half_rn(x), hy = __float2half_rn(y);
    hi = packh2(hx, hy);
    lo = packh2(__float2half_rn(x - __half2float(hx)),
                __float2half_rn(y - __half2float(hy)));
}
__device__ __forceinline__ uint32_t pack2h(float x, float y) {
    return packh2(__float2half_rn(x), __float2half_rn(y));
}
__device__ __forceinline__ float h2sum(uint32_t hi, uint32_t lo, int idx) {
    __half2 h = *(__half2*)&hi;
    __half2 l = *(__half2*)&lo;
    return idx ? (__half2float(__high2half(h)) + __half2float(__high2half(l)))
               : (__half2float(__low2half(h))  + __half2float(__low2half(l)));
}

// ============================ embedding / LN ===================================
__global__ void embed_kernel(const int* __restrict__ X, const float* __restrict__ emb,
                             const float* __restrict__ pe, float* __restrict__ x)
{
    int m = blockIdx.x;
    int t = threadIdx.x;
    int tok = X[m];
    int b = m >> 10;
    float4 e = ((const float4*)(emb + (size_t)tok * DD))[t];
    float4 p = ((const float4*)(pe  + (size_t)b   * DD))[t];
    float4 o;
    o.x = e.x * 32.0f + p.x;  o.y = e.y * 32.0f + p.y;
    o.z = e.z * 32.0f + p.z;  o.w = e.w * 32.0f + p.w;
    ((float4*)(x + (size_t)m * DD))[t] = o;
}

// layernorm -> fp16 output; WRITE_LO controls whether lo residue is emitted
template<bool WRITE_LO>
__global__ void ln_h_kernel(const float* __restrict__ x, const float* __restrict__ g,
                            const float* __restrict__ b,
                            __half* __restrict__ Yh, __half* __restrict__ Yl)
{
    int row = blockIdx.x;
    int t = threadIdx.x;
    float4 v = ((const float4*)(x + (size_t)row * DD))[t];
    float s  = v.x + v.y + v.z + v.w;
    float ss = v.x*v.x + v.y*v.y + v.z*v.z + v.w*v.w;
    #pragma unroll
    for (int o = 16; o; o >>= 1) {
        s  += __shfl_xor_sync(0xFFFFFFFFu, s,  o);
        ss += __shfl_xor_sync(0xFFFFFFFFu, ss, o);
    }
    __shared__ float sm[16];
    __shared__ float s_mu, s_r;
    int w = t >> 5;
    if ((t & 31) == 0) { sm[w] = s; sm[8 + w] = ss; }
    __syncthreads();
    if (t == 0) {
        float a = 0.f, c = 0.f;
        #pragma unroll
        for (int i = 0; i < 8; i++) { a += sm[i]; c += sm[8 + i]; }
        float mu  = a * (1.0f / DD);
        float var = c * (1.0f / DD) - mu * mu;
        s_mu = mu;
        s_r  = rsqrtf(var + 1e-5f);
    }
    __syncthreads();
    float mu = s_mu, r = s_r;
    float4 gv = ((const float4*)g)[t];
    float4 bv = ((const float4*)b)[t];
    float4 o;
    o.x = (v.x - mu) * r * gv.x + bv.x;
    o.y = (v.y - mu) * r * gv.y + bv.y;
    o.z = (v.z - mu) * r * gv.z + bv.z;
    o.w = (v.w - mu) * r * gv.w + bv.w;
    if (WRITE_LO) {
        uint32_t h01, h23, l01, l23;
        split2h(o.x, o.y, h01, l01);
        split2h(o.z, o.w, h23, l23);
        ((uint2*)(Yh + (size_t)row * DD))[t] = make_uint2(h01, h23);
        ((uint2*)(Yl + (size_t)row * DD))[t] = make_uint2(l01, l23);
    } else {
        ((uint2*)(Yh + (size_t)row * DD))[t] =
            make_uint2(pack2h(o.x, o.y), pack2h(o.z, o.w));
    }
}

// ================== weight prep ===============================================
__global__ void transpose_split_kernel(const float* __restrict__ W,
                                       __half* __restrict__ Wh,
                                       __half* __restrict__ Wl,
                                       int K, int N)
{
    __shared__ float t[32][33];
    int l = blockIdx.z;
    W  += (size_t)l * K * N;
    Wh += (size_t)l * N * K;
    Wl += (size_t)l * N * K;
    int n0 = blockIdx.x * 32, k0 = blockIdx.y * 32;
    int tx = threadIdx.x, ty = threadIdx.y;
    #pragma unroll
    for (int i = 0; i < 4; i++)
        t[ty + 8*i][tx] = W[(size_t)(k0 + ty + 8*i) * N + n0 + tx];
    __syncthreads();
    #pragma unroll
    for (int i = 0; i < 4; i++) {
        float v = t[tx][ty + 8*i];
        __half h = __float2half_rn(v);
        __half lo = __float2half_rn(v - __half2float(h));
        size_t oi = (size_t)(n0 + ty + 8*i) * K + k0 + tx;
        Wh[oi] = h; Wl[oi] = lo;
    }
}

__global__ void split_pair_kernel(const float* __restrict__ W,
                                  __half* __restrict__ Wh,
                                  __half* __restrict__ Wl)
{
    size_t i = (size_t)blockIdx.x * blockDim.x + threadIdx.x;
    float4 v = ((const float4*)W)[i];
    uint32_t h01, h23, l01, l23;
    split2h(v.x, v.y, h01, l01);
    split2h(v.z, v.w, h23, l23);
    ((uint2*)Wh)[i] = make_uint2(h01, h23);
    ((uint2*)Wl)[i] = make_uint2(l01, l23);
}

__global__ void tohalf_kernel(const float* __restrict__ W, __half* __restrict__ Wh)
{
    size_t i = (size_t)blockIdx.x * blockDim.x + threadIdx.x;
    float4 v = ((const float4*)W)[i];
    ((uint2*)Wh)[i] = make_uint2(pack2h(v.x, v.y), pack2h(v.z, v.w));
}

// ====================== HMMA fp16x2 GEMM =======================================
// C[M,N] = Ah[M,K](fp16) @ (Bh+Bl)^T[N,K], fp32 accum, 2-term product.
// 128x128 tile, K-step 64, 256 threads (8 warps, 4M x 2N), 3-stage cp.async.
// RESMODE: 0=none, 1=fp32 res, 2=fp16 hi/lo pair res. OUTS: fp16 hi/lo output.
#define A_HI 0
#define B_HI 16384
#define B_LO 32768
#define STAGE_BYTES 49152
#define NSTAGE 3
#define GEMM_DSMEM (NSTAGE*STAGE_BYTES + 1024)

template<int RESMODE, bool OUTS>
__global__ void __launch_bounds__(256, 1)
gemm_hh(const __half* __restrict__ Ah,
        const __half* __restrict__ Bh, const __half* __restrict__ Bl,
        const float* __restrict__ bias,
        const float* __restrict__ resf,
        const __half* __restrict__ resh, const __half* __restrict__ resl,
        float* __restrict__ C,
        __half* __restrict__ Ch, __half* __restrict__ Cl,
        int M, int N, int K)
{
    extern __shared__ char dsm[];
    uint32_t raw = smem_u32(dsm);
    uint32_t tb = (raw + 1023u) & ~1023u;

    const int tid = threadIdx.x;
    const int l   = tid & 31;
    const int wid = tid >> 5;
    const int wm  = (wid & 3) * 32;
    const int wn  = (wid >> 2) * 64;
    const int bm  = blockIdx.x * 128;
    const int bn  = blockIdx.y * 128;

    const uint32_t hi16 = (uint32_t)((l >> 4) * 16);
    uint32_t abase[2], amask[2], bbase[4], bmask[4];
    #pragma unroll
    for (int mi = 0; mi < 2; mi++) {
        uint32_t r = (uint32_t)(wm + mi * 16 + (l & 15));
        abase[mi] = r * 128;
        amask[mi] = (r & 7) << 4;
    }
    #pragma unroll
    for (int nb = 0; nb < 4; nb++) {
        uint32_t r = (uint32_t)(wn + nb * 16 + (l & 15));
        bbase[nb] = r * 128;
        bmask[nb] = (r & 7) << 4;
    }

    float d[2][8][4];
    #pragma unroll
    for (int i = 0; i < 2; i++)
        #pragma unroll
        for (int j = 0; j < 8; j++)
            #pragma unroll
            for (int k = 0; k < 4; k++) d[i][j][k] = 0.f;

    const int nt = K >> 6;

    // per stage: A 128x64 fp16 (16KB) + B hi/lo (32KB), all cp.async
    #define LOAD_T(stg, k0) { \
        uint32_t base = tb + (stg) * STAGE_BYTES; \
        _Pragma("unroll") \
        for (int i = 0; i < 4; i++) { \
            int c = tid + i * 256; int r = c >> 3, s = c & 7; \
            uint32_t off = sw128((uint32_t)(r * 128 + s * 16)); \
            size_t ga = (size_t)(bm + r) * K + (k0) + s * 8; \
            size_t gb = (size_t)(bn + r) * K + (k0) + s * 8; \
            cp16(base + A_HI + off, Ah + ga); \
            cp16(base + B_HI + off, Bh + gb); \
            cp16(base + B_LO + off, Bl + gb); } }

    LOAD_T(0, 0); CP_COMMIT();
    LOAD_T(1, 64); CP_COMMIT();

    for (int t = 0; t < nt; t++) {
        if (t + 1 < nt) { CP_WAIT1(); } else { CP_WAIT0(); }
        __syncthreads();
        {
            uint32_t sb = tb + (uint32_t)(t % NSTAGE) * STAGE_BYTES;
            #pragma unroll
            for (int ks = 0; ks < 4; ks++) {
                const uint32_t ko = (uint32_t)(ks * 32);
                uint32_t aH[2][4];
                #pragma unroll
                for (int mi = 0; mi < 2; mi++) {
                    uint32_t ao = abase[mi] + ((hi16 + ko) ^ amask[mi]);
                    ldsm_x4(aH[mi], sb + A_HI + ao);
                }
                uint32_t bH[8][2], bL[8][2];
                #pragma unroll
                for (int nb = 0; nb < 4; nb++) {
                    uint32_t bo = bbase[nb] + ((hi16 + ko) ^ bmask[nb]);
                    uint32_t r4[4];
                    ldsm_x4(r4, sb + B_HI + bo);
                    bH[2*nb][0] = r4[0]; bH[2*nb][1] = r4[2];
                    bH[2*nb+1][0] = r4[1]; bH[2*nb+1][1] = r4[3];
                    ldsm_x4(r4, sb + B_LO + bo);
                    bL[2*nb][0] = r4[0]; bL[2*nb][1] = r4[2];
                    bL[2*nb+1][0] = r4[1]; bL[2*nb+1][1] = r4[3];
                }
                #pragma unroll
                for (int nj = 0; nj < 8; nj++) {
                    #pragma unroll
                    for (int mi = 0; mi < 2; mi++) {
                        mma_f16(d[mi][nj], aH[mi], bH[nj]);
                        mma_f16(d[mi][nj], aH[mi], bL[nj]);
                    }
                }
            }
        }
        if (t + 2 < nt) {
            LOAD_T((t + 2) % NSTAGE, (t + 2) << 6);
            CP_COMMIT();
        }
    }

    // ---- epilogue ----
    #pragma unroll
    for (int mi = 0; mi < 2; mi++) {
        #pragma unroll
        for (int half = 0; half < 2; half++) {
            int row = bm + wm + mi * 16 + half * 8 + (l >> 2);
            #pragma unroll
            for (int nj = 0; nj < 8; nj++) {
                int col = bn + wn + nj * 8 + 2 * (l & 3);
                float v0 = d[mi][nj][2 * half];
                float v1 = d[mi][nj][2 * half + 1];
                if (bias) { v0 += bias[col]; v1 += bias[col + 1]; }
                size_t ri = (size_t)row * N + col;
                if (RESMODE == 1) {
                    float2 r2 = *(const float2*)&resf[ri];
                    v0 += r2.x; v1 += r2.y;
                } else if (RESMODE == 2) {
                    uint32_t rh = *(const uint32_t*)&resh[ri];
                    uint32_t rl = *(const uint32_t*)&resl[ri];
                    v0 += h2sum(rh, rl, 0);
                    v1 += h2sum(rh, rl, 1);
                }
                if (OUTS) {
                    uint32_t hi, lo;
                    split2h(v0, v1, hi, lo);
                    *(uint32_t*)&Ch[ri] = hi;
                    *(uint32_t*)&Cl[ri] = lo;
                } else {
                    float2 o; o.x = v0; o.y = v1;
                    *(float2*)&C[ri] = o;
                }
            }
        }
    }
}

// ================== HMMA flash attention (fp16x2) ==============================
// Q hi only; K,V hi/lo pairs. 2-term MMAs.
#define AQ_HI 0
#define AKV_OFF 16384
#define AKV_BUF 32768           // [Kh 8K][Kl 8K][Vh 8K][Vl 8K]
#define ATTN_DSMEM (AKV_OFF + 2*AKV_BUF + 1024)

__global__ void __launch_bounds__(256, 1)
attn_mma(const __half* __restrict__ qh, const __half* __restrict__ ql,
         __half* __restrict__ oh)
{
    extern __shared__ char dsm[];
    uint32_t raw = smem_u32(dsm);
    uint32_t tb = (raw + 1023u) & ~1023u;

    const int tid = threadIdx.x;
    const int l   = tid & 31;
    const int w   = tid >> 5;
    const int bh  = blockIdx.y;
    const int b   = bh >> 4;
    const int h   = bh & 15;
    const int q0  = blockIdx.x * 128;
    const size_t hoff = (size_t)h * DH;

    // Q hi tile: 128 x 64 fp16 = 16KB
    #pragma unroll
    for (int i = 0; i < 4; i++) {
        int lin = tid + i * 256;
        int row = lin >> 3, ch = lin & 7;
        const __half* src = qh + (size_t)(b * SS + q0 + row) * (3 * DD) + hoff + ch * 8;
        cp16(tb + AQ_HI + sw128((uint32_t)(row * 128 + ch * 16)), src);
    }
    #define LOAD_KV(t, buf) { \
        _Pragma("unroll") \
        for (int i = 0; i < 8; i++) { \
            int lin = tid + i * 256; \
            int kv = lin >> 10, reg = (lin >> 9) & 1, row = (lin >> 3) & 63, ch = lin & 7; \
            const __half* src = (reg ? ql : qh) \
                + (size_t)(b * SS + (t) * 64 + row) * (3 * DD) \
                + (kv ? 2 * DD : DD) + hoff + ch * 8; \
            cp16(tb + AKV_OFF + (buf) * AKV_BUF + kv * 16384 + reg * 8192 \
                 + sw128((uint32_t)(row * 128 + ch * 16)), src); } }

    LOAD_KV(0, 0); CP_COMMIT();
    LOAD_KV(1, 1); CP_COMMIT();

    float od[8][4];
    #pragma unroll
    for (int j = 0; j < 8; j++)
        #pragma unroll
        for (int k = 0; k < 4; k++) od[j][k] = 0.f;
    float m0 = -1e30f, m1 = -1e30f, l0 = 0.f, l1 = 0.f;

    uint32_t aQh[4][4];
    const uint32_t qrow = (uint32_t)(w * 16 + (l & 15));
    const uint32_t qmask = (qrow & 7) << 4;
    const uint32_t hi16 = (uint32_t)((l >> 4) * 16);

    for (int t = 0; t < 16; t++) {
        const int buf = t & 1;
        if (t < 15) { CP_WAIT1(); } else { CP_WAIT0(); }
        __syncthreads();
        if (t == 0) {
            #pragma unroll
            for (int ks = 0; ks < 4; ks++) {
                uint32_t off = qrow * 128 + ((hi16 + ks * 32) ^ qmask);
                ldsm_x4(aQh[ks], tb + AQ_HI + off);
            }
        }
        const uint32_t sK = tb + AKV_OFF + buf * AKV_BUF;
        const uint32_t sKl = sK + 8192;
        const uint32_t sV = sK + 16384;
        const uint32_t sVl = sK + 24576;

        // ---- scores = Q K^T (fp16x2: Qhi x (Khi+Klo)) ----
        float sc[8][4];
        #pragma unroll
        for (int j = 0; j < 8; j++)
            #pragma unroll
            for (int k = 0; k < 4; k++) sc[j][k] = 0.f;
        #pragma unroll
        for (int ks = 0; ks < 4; ks++) {
            uint32_t bKh[8][2], bKl[8][2];
            #pragma unroll
            for (int nb = 0; nb < 4; nb++) {
                uint32_t row = (uint32_t)(nb * 16 + (l & 15));
                uint32_t off = row * 128 + ((hi16 + ks * 32) ^ ((row & 7) << 4));
                uint32_t r4[4];
                ldsm_x4(r4, sK + off);
                bKh[2*nb][0] = r4[0]; bKh[2*nb][1] = r4[2];
                bKh[2*nb+1][0] = r4[1]; bKh[2*nb+1][1] = r4[3];
                ldsm_x4(r4, sKl + off);
                bKl[2*nb][0] = r4[0]; bKl[2*nb][1] = r4[2];
                bKl[2*nb+1][0] = r4[1]; bKl[2*nb+1][1] = r4[3];
            }
            #pragma unroll
            for (int nj = 0; nj < 8; nj++) {
                mma_f16(sc[nj], aQh[ks], bKh[nj]);
                mma_f16(sc[nj], aQh[ks], bKl[nj]);
            }
        }

        // ---- online softmax ----
        float nm0 = m0, nm1 = m1;
        #pragma unroll
        for (int nj = 0; nj < 8; nj++) {
            nm0 = fmaxf(nm0, fmaxf(sc[nj][0], sc[nj][1]));
            nm1 = fmaxf(nm1, fmaxf(sc[nj][2], sc[nj][3]));
        }
        nm0 = fmaxf(nm0, __shfl_xor_sync(0xFFFFFFFFu, nm0, 1));
        nm0 = fmaxf(nm0, __shfl_xor_sync(0xFFFFFFFFu, nm0, 2));
        nm1 = fmaxf(nm1, __shfl_xor_sync(0xFFFFFFFFu, nm1, 1));
        nm1 = fmaxf(nm1, __shfl_xor_sync(0xFFFFFFFFu, nm1, 2));
        float cor0 = __expf(m0 - nm0), cor1 = __expf(m1 - nm1);
        m0 = nm0; m1 = nm1;
        float rs0 = 0.f, rs1 = 0.f;
        #pragma unroll
        for (int nj = 0; nj < 8; nj++) {
            sc[nj][0] = __expf(sc[nj][0] - nm0);
            sc[nj][1] = __expf(sc[nj][1] - nm0);
            sc[nj][2] = __expf(sc[nj][2] - nm1);
            sc[nj][3] = __expf(sc[nj][3] - nm1);
            rs0 += sc[nj][0] + sc[nj][1];
            rs1 += sc[nj][2] + sc[nj][3];
        }
        rs0 += __shfl_xor_sync(0xFFFFFFFFu, rs0, 1);
        rs0 += __shfl_xor_sync(0xFFFFFFFFu, rs0, 2);
        rs1 += __shfl_xor_sync(0xFFFFFFFFu, rs1, 1);
        rs1 += __shfl_xor_sync(0xFFFFFFFFu, rs1, 2);
        l0 = l0 * cor0 + rs0;
        l1 = l1 * cor1 + rs1;
        #pragma unroll
        for (int nj = 0; nj < 8; nj++) {
            od[nj][0] *= cor0; od[nj][1] *= cor0;
            od[nj][2] *= cor1; od[nj][3] *= cor1;
        }

        // ---- o += P V (fp16x2: Phi x (Vhi+Vlo)) ----
        #pragma unroll
        for (int kj = 0; kj < 4; kj++) {
            uint32_t aPh[4];
            aPh[0] = pack2h(sc[2*kj][0],   sc[2*kj][1]);
            aPh[1] = pack2h(sc[2*kj][2],   sc[2*kj][3]);
            aPh[2] = pack2h(sc[2*kj+1][0], sc[2*kj+1][1]);
            aPh[3] = pack2h(sc[2*kj+1][2], sc[2*kj+1][3]);
            const uint32_t mat = (uint32_t)(l >> 3);
            const uint32_t vrow = (uint32_t)(kj * 16 + (mat & 1) * 8 + (l & 7));
            const uint32_t vmask = (vrow & 7) << 4;
            #pragma unroll
            for (int pp = 0; pp < 4; pp++) {
                uint32_t off = vrow * 128 + (((uint32_t)(pp * 32) + (mat >> 1) * 16) ^ vmask);
                uint32_t rh[4], rl[4];
                ldsm_x4_t(rh, sV + off);
                ldsm_x4_t(rl, sVl + off);
                uint32_t b0h[2] = {rh[0], rh[1]}, b1h[2] = {rh[2], rh[3]};
                uint32_t b0l[2] = {rl[0], rl[1]}, b1l[2] = {rl[2], rl[3]};
                mma_f16(od[2*pp],   aPh, b0h);
                mma_f16(od[2*pp],   aPh, b0l);
                mma_f16(od[2*pp+1], aPh, b1h);
                mma_f16(od[2*pp+1], aPh, b1l);
            }
        }

        __syncthreads();
        if (t + 2 < 16) { LOAD_KV(t + 2, buf); CP_COMMIT(); }
    }

    // ---- write out (hi only; attn out is A-side downstream) ----
    float inv0 = 1.0f / l0, inv1 = 1.0f / l1;
    int row0 = q0 + w * 16 + (l >> 2);
    #pragma unroll
    for (int nj = 0; nj < 8; nj++) {
        int col = (int)hoff + nj * 8 + 2 * (l & 3);
        size_t ri0 = (size_t)(b * SS + row0) * DD + col;
        size_t ri1 = (size_t)(b * SS + row0 + 8) * DD + col;
        *(uint32_t*)&oh[ri0] = pack2h(od[nj][0] * inv0, od[nj][1] * inv0);
        *(uint32_t*)&oh[ri1] = pack2h(od[nj][2] * inv1, od[nj][3] * inv1);
    }
}

// ---------------- launch -------------------------------------------------------
extern "C" void kernel_launch(void* const* d_in, const int* in_sizes, int n_in,
                              void* d_out, int out_size)
{
    const int*   X     = (const int*)  d_in[0];
    const float* emb   = (const float*)d_in[1];
    const float* pe    = (const float*)d_in[2];
    const float* ln1_g = (const float*)d_in[3];
    const float* ln1_b = (const float*)d_in[4];
    const float* wa    = (const float*)d_in[5];
    const float* ba    = (const float*)d_in[6];
    const float* wp    = (const float*)d_in[7];
    const float* bp    = (const float*)d_in[8];
    const float* ln2_g = (const float*)d_in[9];
    const float* ln2_b = (const float*)d_in[10];
    const float* wf    = (const float*)d_in[11];
    const float* bf    = (const float*)d_in[12];
    const float* wout  = (const float*)d_in[13];
    float* logits = (float*)d_out;

    float *x;
    __half *wh, *wl, *qkvh, *qkvl, *hh, *hl, *th, *ah, *xh;
    cudaGetSymbolAddress((void**)&x,    g_x);
    cudaGetSymbolAddress((void**)&wh,   g_wh);
    cudaGetSymbolAddress((void**)&wl,   g_wl);
    cudaGetSymbolAddress((void**)&qkvh, g_qkvh);
    cudaGetSymbolAddress((void**)&qkvl, g_qkvl);
    cudaGetSymbolAddress((void**)&hh,   g_hh);
    cudaGetSymbolAddress((void**)&hl,   g_hl);
    cudaGetSymbolAddress((void**)&th,   g_th);
    cudaGetSymbolAddress((void**)&ah,   g_ah);
    cudaGetSymbolAddress((void**)&xh,   g_xh);

    cudaFuncSetAttribute(gemm_hh<0,true>,  cudaFuncAttributeMaxDynamicSharedMemorySize, GEMM_DSMEM);
    cudaFuncSetAttribute(gemm_hh<2,false>, cudaFuncAttributeMaxDynamicSharedMemorySize, GEMM_DSMEM);
    cudaFuncSetAttribute(gemm_hh<1,false>, cudaFuncAttributeMaxDynamicSharedMemorySize, GEMM_DSMEM);
    cudaFuncSetAttribute(gemm_hh<0,false>, cudaFuncAttributeMaxDynamicSharedMemorySize, GEMM_DSMEM);
    cudaFuncSetAttribute(attn_mma, cudaFuncAttributeMaxDynamicSharedMemorySize, ATTN_DSMEM);

    // weight prep (per replay, HBM-stream bound)
    transpose_split_kernel<<<dim3(3*DD/32, DD/32, LL), dim3(32,8)>>>(
        wa, wh + WA_T_OFF, wl + WA_T_OFF, DD, 3*DD);
    transpose_split_kernel<<<dim3(DD/32, DD/32, LL), dim3(32,8)>>>(
        wp, wh + WP_T_OFF, wl + WP_T_OFF, DD, DD);
    transpose_split_kernel<<<dim3(DD/32, DD/32, LL), dim3(32,8)>>>(
        wf, wh + WF_T_OFF, wl + WF_T_OFF, DD, DD);
    split_pair_kernel<<<(VV*1024/4)/256, 256>>>(wout, wh + WOUT_OFF, wl + WOUT_OFF);

    embed_kernel<<<NTOK, 256>>>(X, emb, pe, x);

    for (int i = 0; i < LL; i++) {
        const float* ba_i = ba + (size_t)i * 3 * DD;
        const float* bp_i = bp + (size_t)i * DD;
        const float* bf_i = bf + (size_t)i * DD;
        const __half* wa_h = wh + WA_T_OFF + (size_t)i * 3*DD * DD;
        const __half* wa_l = wl + WA_T_OFF + (size_t)i * 3*DD * DD;
        const __half* wp_h = wh + WP_T_OFF + (size_t)i * DD * DD;
        const __half* wp_l = wl + WP_T_OFF + (size_t)i * DD * DD;
        const __half* wf_h = wh + WF_T_OFF + (size_t)i * DD * DD;
        const __half* wf_l = wl + WF_T_OFF + (size_t)i * DD * DD;

        // h = LN1(x) -> fp16 pair (pair needed for residual add)
        ln_h_kernel<true><<<NTOK, 256>>>(x, ln1_g + (size_t)i * DD, ln1_b + (size_t)i * DD, hh, hl);
        // qkv = h @ wa + ba -> fp16 pair
        gemm_hh<0,true><<<dim3(NTOK/128, 3*DD/128), 256, GEMM_DSMEM>>>(
            hh, wa_h, wa_l, ba_i, nullptr, nullptr, nullptr,
            nullptr, qkvh, qkvl, NTOK, 3*DD, DD);
        // attention -> fp16 hi
        attn_mma<<<dim3(SS/128, BB*HH), 256, ATTN_DSMEM>>>(qkvh, qkvl, ah);
        // x = h + attn @ wp + bp  (fp32)
        gemm_hh<2,false><<<dim3(NTOK/128, DD/128), 256, GEMM_DSMEM>>>(
            ah, wp_h, wp_l, bp_i, nullptr, hh, hl,
            x, nullptr, nullptr, NTOK, DD, DD);
        // tmp = LN2(x) -> fp16 hi
        ln_h_kernel<false><<<NTOK, 256>>>(x, ln2_g + (size_t)i * DD, ln2_b + (size_t)i * DD, th, nullptr);
        // x = x + tmp @ wf + bf  (fp32)
        gemm_hh<1,false><<<dim3(NTOK/128, DD/128), 256, GEMM_DSMEM>>>(
            th, wf_h, wf_l, bf_i, x, nullptr, nullptr,
            x, nullptr, nullptr, NTOK, DD, DD);
    }

    // logits = x @ wout^T
    tohalf_kernel<<<(NTOK*DD/4)/256, 256>>>(x, xh);
    gemm_hh<0,false><<<dim3(NTOK/128, VV/128), 256, GEMM_DSMEM>>>(
        xh, wh + WOUT_OFF, wl + WOUT_OFF, nullptr, nullptr, nullptr, nullptr,
        logits, nullptr, nullptr, NTOK, VV, DD);
    (void)in_sizes; (void)n_in; (void)out_size;
}

// round 9
// speedup vs baseline: 1.5196x; 1.0670x over previous
#include <cuda_runtime.h>
#include <cuda_fp16.h>
#include <cstdint>

// Problem constants
#define BB 4
#define SS 1024
#define DD 1024
#define HH 16
#define DH 64
#define LL 12
#define VV 32000
#define NTOK (BB*SS)        // 4096 tokens

// ---------------- scratch (static device globals; no allocs allowed) ----------
__device__ float g_x[NTOK * DD];                       // running activations fp32
__device__ __half g_hh[NTOK * DD], g_hl[NTOK * DD];    // post-LN1 hi/lo (residual needs pair)
__device__ __half g_th[NTOK * DD];                     // post-LN2 hi only
__device__ __half g_ah[NTOK * DD];                     // attn out hi only
__device__ __half g_xh[NTOK * DD];                     // final x hi only
__device__ __half g_qkvh[NTOK * 3 * DD];               // qkv hi (Q uses hi; K/V use pair)
__device__ __half g_qkvl[NTOK * 3 * DD];               // qkv lo

// fp16 hi/lo split weights, all in [N,K] layout
#define WA_T_OFF  0
#define WP_T_OFF  (12*3072*1024)
#define WF_T_OFF  (WP_T_OFF + 12*1024*1024)
#define WOUT_OFF  (WF_T_OFF + 12*1024*1024)
#define W_T_TOTAL (WOUT_OFF + VV*1024)
__device__ __half g_wh[W_T_TOTAL];
__device__ __half g_wl[W_T_TOTAL];

// ============================ helpers ==========================================
__device__ __forceinline__ uint32_t smem_u32(const void* p) {
    uint32_t a;
    asm("{ .reg .u64 t; cvta.to.shared.u64 t, %1; cvt.u32.u64 %0, t; }" : "=r"(a) : "l"(p));
    return a;
}
__device__ __forceinline__ uint32_t sw128(uint32_t o) { return o ^ ((o >> 3) & 0x70); }

__device__ __forceinline__ void cp16(uint32_t dst, const void* src) {
    asm volatile("cp.async.cg.shared.global [%0], [%1], 16;" :: "r"(dst), "l"(src) : "memory");
}
#define CP_COMMIT() asm volatile("cp.async.commit_group;" ::: "memory")
#define CP_WAIT0()  asm volatile("cp.async.wait_group 0;" ::: "memory")
#define CP_WAIT1()  asm volatile("cp.async.wait_group 1;" ::: "memory")

__device__ __forceinline__ void ldsm_x4(uint32_t* r, uint32_t addr) {
    asm volatile("ldmatrix.sync.aligned.m8n8.x4.shared.b16 {%0,%1,%2,%3}, [%4];"
        : "=r"(r[0]), "=r"(r[1]), "=r"(r[2]), "=r"(r[3]) : "r"(addr));
}
__device__ __forceinline__ void ldsm_x4_t(uint32_t* r, uint32_t addr) {
    asm volatile("ldmatrix.sync.aligned.m8n8.x4.trans.shared.b16 {%0,%1,%2,%3}, [%4];"
        : "=r"(r[0]), "=r"(r[1]), "=r"(r[2]), "=r"(r[3]) : "r"(addr));
}
__device__ __forceinline__ void mma_f16(float* d, const uint32_t* a, const uint32_t* b) {
    asm volatile(
        "mma.sync.aligned.m16n8k16.row.col.f32.f16.f16.f32 "
        "{%0,%1,%2,%3}, {%4,%5,%6,%7}, {%8,%9}, {%0,%1,%2,%3};"
        : "+f"(d[0]), "+f"(d[1]), "+f"(d[2]), "+f"(d[3])
        : "r"(a[0]), "r"(a[1]), "r"(a[2]), "r"(a[3]), "r"(b[0]), "r"(b[1]));
}

__device__ __forceinline__ uint32_t packh2(__half a, __half b) {
    __half2 h = __halves2half2(a, b);
    return *(uint32_t*)&h;
}
__device__ __forceinline__ void split2h(float x, float y, uint32_t& hi, uint32_t& lo) {
    __half hx = __float2half_rn(x), hy = __float2half_rn(y);
    hi = packh2(hx, hy);
    lo = packh2(__float2half_rn(x - __half2float(hx)),
                __float2half_rn(y - __half2float(hy)));
}
__device__ __forceinline__ uint32_t pack2h(float x, float y) {
    return packh2(__float2half_rn(x), __float2half_rn(y));
}
__device__ __forceinline__ float h2sum(uint32_t hi, uint32_t lo, int idx) {
    __half2 h = *(__half2*)&hi;
    __half2 l = *(__half2*)&lo;
    return idx ? (__half2float(__high2half(h)) + __half2float(__high2half(l)))
               : (__half2float(__low2half(h))  + __half2float(__low2half(l)));
}

// ============================ embedding / LN ===================================
__global__ void embed_kernel(const int* __restrict__ X, const float* __restrict__ emb,
                             const float* __restrict__ pe, float* __restrict__ x)
{
    int m = blockIdx.x;
    int t = threadIdx.x;
    int tok = X[m];
    int b = m >> 10;
    float4 e = ((const float4*)(emb + (size_t)tok * DD))[t];
    float4 p = ((const float4*)(pe  + (size_t)b   * DD))[t];
    float4 o;
    o.x = e.x * 32.0f + p.x;  o.y = e.y * 32.0f + p.y;
    o.z = e.z * 32.0f + p.z;  o.w = e.w * 32.0f + p.w;
    ((float4*)(x + (size_t)m * DD))[t] = o;
}

template<bool WRITE_LO>
__global__ void ln_h_kernel(const float* __restrict__ x, const float* __restrict__ g,
                            const float* __restrict__ b,
                            __half* __restrict__ Yh, __half* __restrict__ Yl)
{
    int row = blockIdx.x;
    int t = threadIdx.x;
    float4 v = ((const float4*)(x + (size_t)row * DD))[t];
    float s  = v.x + v.y + v.z + v.w;
    float ss = v.x*v.x + v.y*v.y + v.z*v.z + v.w*v.w;
    #pragma unroll
    for (int o = 16; o; o >>= 1) {
        s  += __shfl_xor_sync(0xFFFFFFFFu, s,  o);
        ss += __shfl_xor_sync(0xFFFFFFFFu, ss, o);
    }
    __shared__ float sm[16];
    __shared__ float s_mu, s_r;
    int w = t >> 5;
    if ((t & 31) == 0) { sm[w] = s; sm[8 + w] = ss; }
    __syncthreads();
    if (t == 0) {
        float a = 0.f, c = 0.f;
        #pragma unroll
        for (int i = 0; i < 8; i++) { a += sm[i]; c += sm[8 + i]; }
        float mu  = a * (1.0f / DD);
        float var = c * (1.0f / DD) - mu * mu;
        s_mu = mu;
        s_r  = rsqrtf(var + 1e-5f);
    }
    __syncthreads();
    float mu = s_mu, r = s_r;
    float4 gv = ((const float4*)g)[t];
    float4 bv = ((const float4*)b)[t];
    float4 o;
    o.x = (v.x - mu) * r * gv.x + bv.x;
    o.y = (v.y - mu) * r * gv.y + bv.y;
    o.z = (v.z - mu) * r * gv.z + bv.z;
    o.w = (v.w - mu) * r * gv.w + bv.w;
    if (WRITE_LO) {
        uint32_t h01, h23, l01, l23;
        split2h(o.x, o.y, h01, l01);
        split2h(o.z, o.w, h23, l23);
        ((uint2*)(Yh + (size_t)row * DD))[t] = make_uint2(h01, h23);
        ((uint2*)(Yl + (size_t)row * DD))[t] = make_uint2(l01, l23);
    } else {
        ((uint2*)(Yh + (size_t)row * DD))[t] =
            make_uint2(pack2h(o.x, o.y), pack2h(o.z, o.w));
    }
}

// ================== weight prep ===============================================
__global__ void transpose_split_kernel(const float* __restrict__ W,
                                       __half* __restrict__ Wh,
                                       __half* __restrict__ Wl,
                                       int K, int N)
{
    __shared__ float t[32][33];
    int l = blockIdx.z;
    W  += (size_t)l * K * N;
    Wh += (size_t)l * N * K;
    Wl += (size_t)l * N * K;
    int n0 = blockIdx.x * 32, k0 = blockIdx.y * 32;
    int tx = threadIdx.x, ty = threadIdx.y;
    #pragma unroll
    for (int i = 0; i < 4; i++)
        t[ty + 8*i][tx] = W[(size_t)(k0 + ty + 8*i) * N + n0 + tx];
    __syncthreads();
    #pragma unroll
    for (int i = 0; i < 4; i++) {
        float v = t[tx][ty + 8*i];
        __half h = __float2half_rn(v);
        __half lo = __float2half_rn(v - __half2float(h));
        size_t oi = (size_t)(n0 + ty + 8*i) * K + k0 + tx;
        Wh[oi] = h; Wl[oi] = lo;
    }
}

__global__ void split_pair_kernel(const float* __restrict__ W,
                                  __half* __restrict__ Wh,
                                  __half* __restrict__ Wl)
{
    size_t i = (size_t)blockIdx.x * blockDim.x + threadIdx.x;
    float4 v = ((const float4*)W)[i];
    uint32_t h01, h23, l01, l23;
    split2h(v.x, v.y, h01, l01);
    split2h(v.z, v.w, h23, l23);
    ((uint2*)Wh)[i] = make_uint2(h01, h23);
    ((uint2*)Wl)[i] = make_uint2(l01, l23);
}

__global__ void tohalf_kernel(const float* __restrict__ W, __half* __restrict__ Wh)
{
    size_t i = (size_t)blockIdx.x * blockDim.x + threadIdx.x;
    float4 v = ((const float4*)W)[i];
    ((uint2*)Wh)[i] = make_uint2(pack2h(v.x, v.y), pack2h(v.z, v.w));
}

// ====================== HMMA fp16x2 GEMM =======================================
// C[M,N] = Ah[M,K](fp16) @ (Bh+Bl)^T[N,K], fp32 accum, 2-term product.
// 128x128 tile, K-step 64, 256 threads (8 warps, 4M x 2N).
// 2-stage cp.async pipeline, 2 CTAs/SM for cross-CTA latency hiding.
#define A_HI 0
#define B_HI 16384
#define B_LO 32768
#define STAGE_BYTES 49152
#define GEMM_DSMEM (2*STAGE_BYTES + 1024)

template<int RESMODE, bool OUTS>
__global__ void __launch_bounds__(256, 2)
gemm_hh(const __half* __restrict__ Ah,
        const __half* __restrict__ Bh, const __half* __restrict__ Bl,
        const float* __restrict__ bias,
        const float* __restrict__ resf,
        const __half* __restrict__ resh, const __half* __restrict__ resl,
        float* __restrict__ C,
        __half* __restrict__ Ch, __half* __restrict__ Cl,
        int M, int N, int K)
{
    extern __shared__ char dsm[];
    uint32_t raw = smem_u32(dsm);
    uint32_t tb = (raw + 1023u) & ~1023u;

    const int tid = threadIdx.x;
    const int l   = tid & 31;
    const int wid = tid >> 5;
    const int wm  = (wid & 3) * 32;
    const int wn  = (wid >> 2) * 64;
    const int bm  = blockIdx.x * 128;
    const int bn  = blockIdx.y * 128;

    const uint32_t hi16 = (uint32_t)((l >> 4) * 16);
    uint32_t abase[2], amask[2], bbase[4], bmask[4];
    #pragma unroll
    for (int mi = 0; mi < 2; mi++) {
        uint32_t r = (uint32_t)(wm + mi * 16 + (l & 15));
        abase[mi] = r * 128;
        amask[mi] = (r & 7) << 4;
    }
    #pragma unroll
    for (int nb = 0; nb < 4; nb++) {
        uint32_t r = (uint32_t)(wn + nb * 16 + (l & 15));
        bbase[nb] = r * 128;
        bmask[nb] = (r & 7) << 4;
    }

    float d[2][8][4];
    #pragma unroll
    for (int i = 0; i < 2; i++)
        #pragma unroll
        for (int j = 0; j < 8; j++)
            #pragma unroll
            for (int k = 0; k < 4; k++) d[i][j][k] = 0.f;

    const int nt = K >> 6;

    #define LOAD_T(stg, k0) { \
        uint32_t base = tb + (stg) * STAGE_BYTES; \
        _Pragma("unroll") \
        for (int i = 0; i < 4; i++) { \
            int c = tid + i * 256; int r = c >> 3, s = c & 7; \
            uint32_t off = sw128((uint32_t)(r * 128 + s * 16)); \
            size_t ga = (size_t)(bm + r) * K + (k0) + s * 8; \
            size_t gb = (size_t)(bn + r) * K + (k0) + s * 8; \
            cp16(base + A_HI + off, Ah + ga); \
            cp16(base + B_HI + off, Bh + gb); \
            cp16(base + B_LO + off, Bl + gb); } }

    LOAD_T(0, 0); CP_COMMIT();
    LOAD_T(1, 64); CP_COMMIT();

    for (int t = 0; t < nt; t++) {
        if (t + 1 < nt) { CP_WAIT1(); } else { CP_WAIT0(); }
        __syncthreads();
        {
            uint32_t sb = tb + (uint32_t)(t & 1) * STAGE_BYTES;
            #pragma unroll
            for (int ks = 0; ks < 4; ks++) {
                const uint32_t ko = (uint32_t)(ks * 32);
                uint32_t aH[2][4];
                #pragma unroll
                for (int mi = 0; mi < 2; mi++) {
                    uint32_t ao = abase[mi] + ((hi16 + ko) ^ amask[mi]);
                    ldsm_x4(aH[mi], sb + A_HI + ao);
                }
                uint32_t bH[8][2], bL[8][2];
                #pragma unroll
                for (int nb = 0; nb < 4; nb++) {
                    uint32_t bo = bbase[nb] + ((hi16 + ko) ^ bmask[nb]);
                    uint32_t r4[4];
                    ldsm_x4(r4, sb + B_HI + bo);
                    bH[2*nb][0] = r4[0]; bH[2*nb][1] = r4[2];
                    bH[2*nb+1][0] = r4[1]; bH[2*nb+1][1] = r4[3];
                    ldsm_x4(r4, sb + B_LO + bo);
                    bL[2*nb][0] = r4[0]; bL[2*nb][1] = r4[2];
                    bL[2*nb+1][0] = r4[1]; bL[2*nb+1][1] = r4[3];
                }
                #pragma unroll
                for (int nj = 0; nj < 8; nj++) {
                    #pragma unroll
                    for (int mi = 0; mi < 2; mi++) {
                        mma_f16(d[mi][nj], aH[mi], bH[nj]);
                        mma_f16(d[mi][nj], aH[mi], bL[nj]);
                    }
                }
            }
        }
        if (t + 2 < nt) {
            __syncthreads();            // all warps done reading buf (t&1)
            LOAD_T(t & 1, (t + 2) << 6);
            CP_COMMIT();
        }
    }

    // ---- epilogue ----
    #pragma unroll
    for (int mi = 0; mi < 2; mi++) {
        #pragma unroll
        for (int half = 0; half < 2; half++) {
            int row = bm + wm + mi * 16 + half * 8 + (l >> 2);
            #pragma unroll
            for (int nj = 0; nj < 8; nj++) {
                int col = bn + wn + nj * 8 + 2 * (l & 3);
                float v0 = d[mi][nj][2 * half];
                float v1 = d[mi][nj][2 * half + 1];
                if (bias) { v0 += bias[col]; v1 += bias[col + 1]; }
                size_t ri = (size_t)row * N + col;
                if (RESMODE == 1) {
                    float2 r2 = *(const float2*)&resf[ri];
                    v0 += r2.x; v1 += r2.y;
                } else if (RESMODE == 2) {
                    uint32_t rh = *(const uint32_t*)&resh[ri];
                    uint32_t rl = *(const uint32_t*)&resl[ri];
                    v0 += h2sum(rh, rl, 0);
                    v1 += h2sum(rh, rl, 1);
                }
                if (OUTS) {
                    uint32_t hi, lo;
                    split2h(v0, v1, hi, lo);
                    *(uint32_t*)&Ch[ri] = hi;
                    *(uint32_t*)&Cl[ri] = lo;
                } else {
                    float2 o; o.x = v0; o.y = v1;
                    *(float2*)&C[ri] = o;
                }
            }
        }
    }
}

// ================== HMMA flash attention (fp16x2) ==============================
// Q hi only; K,V hi/lo pairs. 2 CTAs/SM.
#define AQ_HI 0
#define AKV_OFF 16384
#define AKV_BUF 32768           // [Kh 8K][Kl 8K][Vh 8K][Vl 8K]
#define ATTN_DSMEM (AKV_OFF + 2*AKV_BUF + 1024)

__global__ void __launch_bounds__(256, 2)
attn_mma(const __half* __restrict__ qh, const __half* __restrict__ ql,
         __half* __restrict__ oh)
{
    extern __shared__ char dsm[];
    uint32_t raw = smem_u32(dsm);
    uint32_t tb = (raw + 1023u) & ~1023u;

    const int tid = threadIdx.x;
    const int l   = tid & 31;
    const int w   = tid >> 5;
    const int bh  = blockIdx.y;
    const int b   = bh >> 4;
    const int h   = bh & 15;
    const int q0  = blockIdx.x * 128;
    const size_t hoff = (size_t)h * DH;

    #pragma unroll
    for (int i = 0; i < 4; i++) {
        int lin = tid + i * 256;
        int row = lin >> 3, ch = lin & 7;
        const __half* src = qh + (size_t)(b * SS + q0 + row) * (3 * DD) + hoff + ch * 8;
        cp16(tb + AQ_HI + sw128((uint32_t)(row * 128 + ch * 16)), src);
    }
    #define LOAD_KV(t, buf) { \
        _Pragma("unroll") \
        for (int i = 0; i < 8; i++) { \
            int lin = tid + i * 256; \
            int kv = lin >> 10, reg = (lin >> 9) & 1, row = (lin >> 3) & 63, ch = lin & 7; \
            const __half* src = (reg ? ql : qh) \
                + (size_t)(b * SS + (t) * 64 + row) * (3 * DD) \
                + (kv ? 2 * DD : DD) + hoff + ch * 8; \
            cp16(tb + AKV_OFF + (buf) * AKV_BUF + kv * 16384 + reg * 8192 \
                 + sw128((uint32_t)(row * 128 + ch * 16)), src); } }

    LOAD_KV(0, 0); CP_COMMIT();
    LOAD_KV(1, 1); CP_COMMIT();

    float od[8][4];
    #pragma unroll
    for (int j = 0; j < 8; j++)
        #pragma unroll
        for (int k = 0; k < 4; k++) od[j][k] = 0.f;
    float m0 = -1e30f, m1 = -1e30f, l0 = 0.f, l1 = 0.f;

    uint32_t aQh[4][4];
    const uint32_t qrow = (uint32_t)(w * 16 + (l & 15));
    const uint32_t qmask = (qrow & 7) << 4;
    const uint32_t hi16 = (uint32_t)((l >> 4) * 16);

    for (int t = 0; t < 16; t++) {
        const int buf = t & 1;
        if (t < 15) { CP_WAIT1(); } else { CP_WAIT0(); }
        __syncthreads();
        if (t == 0) {
            #pragma unroll
            for (int ks = 0; ks < 4; ks++) {
                uint32_t off = qrow * 128 + ((hi16 + ks * 32) ^ qmask);
                ldsm_x4(aQh[ks], tb + AQ_HI + off);
            }
        }
        const uint32_t sK = tb + AKV_OFF + buf * AKV_BUF;
        const uint32_t sKl = sK + 8192;
        const uint32_t sV = sK + 16384;
        const uint32_t sVl = sK + 24576;

        float sc[8][4];
        #pragma unroll
        for (int j = 0; j < 8; j++)
            #pragma unroll
            for (int k = 0; k < 4; k++) sc[j][k] = 0.f;
        #pragma unroll
        for (int ks = 0; ks < 4; ks++) {
            uint32_t bKh[8][2], bKl[8][2];
            #pragma unroll
            for (int nb = 0; nb < 4; nb++) {
                uint32_t row = (uint32_t)(nb * 16 + (l & 15));
                uint32_t off = row * 128 + ((hi16 + ks * 32) ^ ((row & 7) << 4));
                uint32_t r4[4];
                ldsm_x4(r4, sK + off);
                bKh[2*nb][0] = r4[0]; bKh[2*nb][1] = r4[2];
                bKh[2*nb+1][0] = r4[1]; bKh[2*nb+1][1] = r4[3];
                ldsm_x4(r4, sKl + off);
                bKl[2*nb][0] = r4[0]; bKl[2*nb][1] = r4[2];
                bKl[2*nb+1][0] = r4[1]; bKl[2*nb+1][1] = r4[3];
            }
            #pragma unroll
            for (int nj = 0; nj < 8; nj++) {
                mma_f16(sc[nj], aQh[ks], bKh[nj]);
                mma_f16(sc[nj], aQh[ks], bKl[nj]);
            }
        }

        float nm0 = m0, nm1 = m1;
        #pragma unroll
        for (int nj = 0; nj < 8; nj++) {
            nm0 = fmaxf(nm0, fmaxf(sc[nj][0], sc[nj][1]));
            nm1 = fmaxf(nm1, fmaxf(sc[nj][2], sc[nj][3]));
        }
        nm0 = fmaxf(nm0, __shfl_xor_sync(0xFFFFFFFFu, nm0, 1));
        nm0 = fmaxf(nm0, __shfl_xor_sync(0xFFFFFFFFu, nm0, 2));
        nm1 = fmaxf(nm1, __shfl_xor_sync(0xFFFFFFFFu, nm1, 1));
        nm1 = fmaxf(nm1, __shfl_xor_sync(0xFFFFFFFFu, nm1, 2));
        float cor0 = __expf(m0 - nm0), cor1 = __expf(m1 - nm1);
        m0 = nm0; m1 = nm1;
        float rs0 = 0.f, rs1 = 0.f;
        #pragma unroll
        for (int nj = 0; nj < 8; nj++) {
            sc[nj][0] = __expf(sc[nj][0] - nm0);
            sc[nj][1] = __expf(sc[nj][1] - nm0);
            sc[nj][2] = __expf(sc[nj][2] - nm1);
            sc[nj][3] = __expf(sc[nj][3] - nm1);
            rs0 += sc[nj][0] + sc[nj][1];
            rs1 += sc[nj][2] + sc[nj][3];
        }
        rs0 += __shfl_xor_sync(0xFFFFFFFFu, rs0, 1);
        rs0 += __shfl_xor_sync(0xFFFFFFFFu, rs0, 2);
        rs1 += __shfl_xor_sync(0xFFFFFFFFu, rs1, 1);
        rs1 += __shfl_xor_sync(0xFFFFFFFFu, rs1, 2);
        l0 = l0 * cor0 + rs0;
        l1 = l1 * cor1 + rs1;
        #pragma unroll
        for (int nj = 0; nj < 8; nj++) {
            od[nj][0] *= cor0; od[nj][1] *= cor0;
            od[nj][2] *= cor1; od[nj][3] *= cor1;
        }

        #pragma unroll
        for (int kj = 0; kj < 4; kj++) {
            uint32_t aPh[4];
            aPh[0] = pack2h(sc[2*kj][0],   sc[2*kj][1]);
            aPh[1] = pack2h(sc[2*kj][2],   sc[2*kj][3]);
            aPh[2] = pack2h(sc[2*kj+1][0], sc[2*kj+1][1]);
            aPh[3] = pack2h(sc[2*kj+1][2], sc[2*kj+1][3]);
            const uint32_t mat = (uint32_t)(l >> 3);
            const uint32_t vrow = (uint32_t)(kj * 16 + (mat & 1) * 8 + (l & 7));
            const uint32_t vmask = (vrow & 7) << 4;
            #pragma unroll
            for (int pp = 0; pp < 4; pp++) {
                uint32_t off = vrow * 128 + (((uint32_t)(pp * 32) + (mat >> 1) * 16) ^ vmask);
                uint32_t rh[4], rl[4];
                ldsm_x4_t(rh, sV + off);
                ldsm_x4_t(rl, sVl + off);
                uint32_t b0h[2] = {rh[0], rh[1]}, b1h[2] = {rh[2], rh[3]};
                uint32_t b0l[2] = {rl[0], rl[1]}, b1l[2] = {rl[2], rl[3]};
                mma_f16(od[2*pp],   aPh, b0h);
                mma_f16(od[2*pp],   aPh, b0l);
                mma_f16(od[2*pp+1], aPh, b1h);
                mma_f16(od[2*pp+1], aPh, b1l);
            }
        }

        __syncthreads();
        if (t + 2 < 16) { LOAD_KV(t + 2, buf); CP_COMMIT(); }
    }

    float inv0 = 1.0f / l0, inv1 = 1.0f / l1;
    int row0 = q0 + w * 16 + (l >> 2);
    #pragma unroll
    for (int nj = 0; nj < 8; nj++) {
        int col = (int)hoff + nj * 8 + 2 * (l & 3);
        size_t ri0 = (size_t)(b * SS + row0) * DD + col;
        size_t ri1 = (size_t)(b * SS + row0 + 8) * DD + col;
        *(uint32_t*)&oh[ri0] = pack2h(od[nj][0] * inv0, od[nj][1] * inv0);
        *(uint32_t*)&oh[ri1] = pack2h(od[nj][2] * inv1, od[nj][3] * inv1);
    }
}

// ---------------- launch -------------------------------------------------------
extern "C" void kernel_launch(void* const* d_in, const int* in_sizes, int n_in,
                              void* d_out, int out_size)
{
    const int*   X     = (const int*)  d_in[0];
    const float* emb   = (const float*)d_in[1];
    const float* pe    = (const float*)d_in[2];
    const float* ln1_g = (const float*)d_in[3];
    const float* ln1_b = (const float*)d_in[4];
    const float* wa    = (const float*)d_in[5];
    const float* ba    = (const float*)d_in[6];
    const float* wp    = (const float*)d_in[7];
    const float* bp    = (const float*)d_in[8];
    const float* ln2_g = (const float*)d_in[9];
    const float* ln2_b = (const float*)d_in[10];
    const float* wf    = (const float*)d_in[11];
    const float* bf    = (const float*)d_in[12];
    const float* wout  = (const float*)d_in[13];
    float* logits = (float*)d_out;

    float *x;
    __half *wh, *wl, *qkvh, *qkvl, *hh, *hl, *th, *ah, *xh;
    cudaGetSymbolAddress((void**)&x,    g_x);
    cudaGetSymbolAddress((void**)&wh,   g_wh);
    cudaGetSymbolAddress((void**)&wl,   g_wl);
    cudaGetSymbolAddress((void**)&qkvh, g_qkvh);
    cudaGetSymbolAddress((void**)&qkvl, g_qkvl);
    cudaGetSymbolAddress((void**)&hh,   g_hh);
    cudaGetSymbolAddress((void**)&hl,   g_hl);
    cudaGetSymbolAddress((void**)&th,   g_th);
    cudaGetSymbolAddress((void**)&ah,   g_ah);
    cudaGetSymbolAddress((void**)&xh,   g_xh);

    cudaFuncSetAttribute(gemm_hh<0,true>,  cudaFuncAttributeMaxDynamicSharedMemorySize, GEMM_DSMEM);
    cudaFuncSetAttribute(gemm_hh<2,false>, cudaFuncAttributeMaxDynamicSharedMemorySize, GEMM_DSMEM);
    cudaFuncSetAttribute(gemm_hh<1,false>, cudaFuncAttributeMaxDynamicSharedMemorySize, GEMM_DSMEM);
    cudaFuncSetAttribute(gemm_hh<0,false>, cudaFuncAttributeMaxDynamicSharedMemorySize, GEMM_DSMEM);
    cudaFuncSetAttribute(attn_mma, cudaFuncAttributeMaxDynamicSharedMemorySize, ATTN_DSMEM);

    // weight prep (per replay, HBM-stream bound)
    transpose_split_kernel<<<dim3(3*DD/32, DD/32, LL), dim3(32,8)>>>(
        wa, wh + WA_T_OFF, wl + WA_T_OFF, DD, 3*DD);
    transpose_split_kernel<<<dim3(DD/32, DD/32, LL), dim3(32,8)>>>(
        wp, wh + WP_T_OFF, wl + WP_T_OFF, DD, DD);
    transpose_split_kernel<<<dim3(DD/32, DD/32, LL), dim3(32,8)>>>(
        wf, wh + WF_T_OFF, wl + WF_T_OFF, DD, DD);
    split_pair_kernel<<<(VV*1024/4)/256, 256>>>(wout, wh + WOUT_OFF, wl + WOUT_OFF);

    embed_kernel<<<NTOK, 256>>>(X, emb, pe, x);

    for (int i = 0; i < LL; i++) {
        const float* ba_i = ba + (size_t)i * 3 * DD;
        const float* bp_i = bp + (size_t)i * DD;
        const float* bf_i = bf + (size_t)i * DD;
        const __half* wa_h = wh + WA_T_OFF + (size_t)i * 3*DD * DD;
        const __half* wa_l = wl + WA_T_OFF + (size_t)i * 3*DD * DD;
        const __half* wp_h = wh + WP_T_OFF + (size_t)i * DD * DD;
        const __half* wp_l = wl + WP_T_OFF + (size_t)i * DD * DD;
        const __half* wf_h = wh + WF_T_OFF + (size_t)i * DD * DD;
        const __half* wf_l = wl + WF_T_OFF + (size_t)i * DD * DD;

        ln_h_kernel<true><<<NTOK, 256>>>(x, ln1_g + (size_t)i * DD, ln1_b + (size_t)i * DD, hh, hl);
        gemm_hh<0,true><<<dim3(NTOK/128, 3*DD/128), 256, GEMM_DSMEM>>>(
            hh, wa_h, wa_l, ba_i, nullptr, nullptr, nullptr,
            nullptr, qkvh, qkvl, NTOK, 3*DD, DD);
        attn_mma<<<dim3(SS/128, BB*HH), 256, ATTN_DSMEM>>>(qkvh, qkvl, ah);
        gemm_hh<2,false><<<dim3(NTOK/128, DD/128), 256, GEMM_DSMEM>>>(
            ah, wp_h, wp_l, bp_i, nullptr, hh, hl,
            x, nullptr, nullptr, NTOK, DD, DD);
        ln_h_kernel<false><<<NTOK, 256>>>(x, ln2_g + (size_t)i * DD, ln2_b + (size_t)i * DD, th, nullptr);
        gemm_hh<1,false><<<dim3(NTOK/128, DD/128), 256, GEMM_DSMEM>>>(
            th, wf_h, wf_l, bf_i, x, nullptr, nullptr,
            x, nullptr, nullptr, NTOK, DD, DD);
    }

    tohalf_kernel<<<(NTOK*DD/4)/256, 256>>>(x, xh);
    gemm_hh<0,false><<<dim3(NTOK/128, VV/128), 256, GEMM_DSMEM>>>(
        xh, wh + WOUT_OFF, wl + WOUT_OFF, nullptr, nullptr, nullptr, nullptr,
        logits, nullptr, nullptr, NTOK, VV, DD);
    (void)in_sizes; (void)n_in; (void)out_size;
}

// round 10
// speedup vs baseline: 1.5493x; 1.0195x over previous
#include <cuda_runtime.h>
#include <cuda_fp16.h>
#include <cstdint>

// Problem constants
#define BB 4
#define SS 1024
#define DD 1024
#define HH 16
#define DH 64
#define LL 12
#define VV 32000
#define NTOK (BB*SS)        // 4096 tokens

// ---------------- scratch (static device globals; no allocs allowed) ----------
__device__ float g_x[NTOK * DD];                       // running activations fp32
__device__ __half g_hh[NTOK * DD], g_hl[NTOK * DD];    // post-LN1 hi/lo (residual needs pair)
__device__ __half g_th[NTOK * DD];                     // post-LN2 hi only
__device__ __half g_ah[NTOK * DD];                     // attn out hi only
__device__ __half g_xh[NTOK * DD];                     // final x hi only
__device__ __half g_qkvh[NTOK * 3 * DD];               // qkv hi (Q uses hi; K/V use pair)
__device__ __half g_qkvl[NTOK * 3 * DD];               // qkv lo

// fp16 hi/lo split weights, all in [N,K] layout
#define WA_T_OFF  0
#define WP_T_OFF  (12*3072*1024)
#define WF_T_OFF  (WP_T_OFF + 12*1024*1024)
#define WOUT_OFF  (WF_T_OFF + 12*1024*1024)
#define W_T_TOTAL (WOUT_OFF + VV*1024)
__device__ __half g_wh[W_T_TOTAL];
__device__ __half g_wl[W_T_TOTAL];

// ============================ helpers ==========================================
__device__ __forceinline__ uint32_t smem_u32(const void* p) {
    uint32_t a;
    asm("{ .reg .u64 t; cvta.to.shared.u64 t, %1; cvt.u32.u64 %0, t; }" : "=r"(a) : "l"(p));
    return a;
}
__device__ __forceinline__ uint32_t sw128(uint32_t o) { return o ^ ((o >> 3) & 0x70); }

__device__ __forceinline__ void cp16(uint32_t dst, const void* src) {
    asm volatile("cp.async.cg.shared.global [%0], [%1], 16;" :: "r"(dst), "l"(src) : "memory");
}
#define CP_COMMIT() asm volatile("cp.async.commit_group;" ::: "memory")
#define CP_WAIT0()  asm volatile("cp.async.wait_group 0;" ::: "memory")

__device__ __forceinline__ void ldsm_x4(uint32_t* r, uint32_t addr) {
    asm volatile("ldmatrix.sync.aligned.m8n8.x4.shared.b16 {%0,%1,%2,%3}, [%4];"
        : "=r"(r[0]), "=r"(r[1]), "=r"(r[2]), "=r"(r[3]) : "r"(addr));
}
__device__ __forceinline__ void ldsm_x4_t(uint32_t* r, uint32_t addr) {
    asm volatile("ldmatrix.sync.aligned.m8n8.x4.trans.shared.b16 {%0,%1,%2,%3}, [%4];"
        : "=r"(r[0]), "=r"(r[1]), "=r"(r[2]), "=r"(r[3]) : "r"(addr));
}
__device__ __forceinline__ void mma_f16(float* d, const uint32_t* a, const uint32_t* b) {
    asm volatile(
        "mma.sync.aligned.m16n8k16.row.col.f32.f16.f16.f32 "
        "{%0,%1,%2,%3}, {%4,%5,%6,%7}, {%8,%9}, {%0,%1,%2,%3};"
        : "+f"(d[0]), "+f"(d[1]), "+f"(d[2]), "+f"(d[3])
        : "r"(a[0]), "r"(a[1]), "r"(a[2]), "r"(a[3]), "r"(b[0]), "r"(b[1]));
}

__device__ __forceinline__ uint32_t packh2(__half a, __half b) {
    __half2 h = __halves2half2(a, b);
    return *(uint32_t*)&h;
}
__device__ __forceinline__ void split2h(float x, float y, uint32_t& hi, uint32_t& lo) {
    __half hx = __float2half_rn(x), hy = __float2half_rn(y);
    hi = packh2(hx, hy);
    lo = packh2(__float2half_rn(x - __half2float(hx)),
                __float2half_rn(y - __half2float(hy)));
}
__device__ __forceinline__ uint32_t pack2h(float x, float y) {
    return packh2(__float2half_rn(x), __float2half_rn(y));
}
__device__ __forceinline__ float h2sum(uint32_t hi, uint32_t lo, int idx) {
    __half2 h = *(__half2*)&hi;
    __half2 l = *(__half2*)&lo;
    return idx ? (__half2float(__high2half(h)) + __half2float(__high2half(l)))
               : (__half2float(__low2half(h))  + __half2float(__low2half(l)));
}

// ============================ embedding / LN ===================================
__global__ void embed_kernel(const int* __restrict__ X, const float* __restrict__ emb,
                             const float* __restrict__ pe, float* __restrict__ x)
{
    int m = blockIdx.x;
    int t = threadIdx.x;
    int tok = X[m];
    int b = m >> 10;
    float4 e = ((const float4*)(emb + (size_t)tok * DD))[t];
    float4 p = ((const float4*)(pe  + (size_t)b   * DD))[t];
    float4 o;
    o.x = e.x * 32.0f + p.x;  o.y = e.y * 32.0f + p.y;
    o.z = e.z * 32.0f + p.z;  o.w = e.w * 32.0f + p.w;
    ((float4*)(x + (size_t)m * DD))[t] = o;
}

template<bool WRITE_LO>
__global__ void ln_h_kernel(const float* __restrict__ x, const float* __restrict__ g,
                            const float* __restrict__ b,
                            __half* __restrict__ Yh, __half* __restrict__ Yl)
{
    int row = blockIdx.x;
    int t = threadIdx.x;
    float4 v = ((const float4*)(x + (size_t)row * DD))[t];
    float s  = v.x + v.y + v.z + v.w;
    float ss = v.x*v.x + v.y*v.y + v.z*v.z + v.w*v.w;
    #pragma unroll
    for (int o = 16; o; o >>= 1) {
        s  += __shfl_xor_sync(0xFFFFFFFFu, s,  o);
        ss += __shfl_xor_sync(0xFFFFFFFFu, ss, o);
    }
    __shared__ float sm[16];
    __shared__ float s_mu, s_r;
    int w = t >> 5;
    if ((t & 31) == 0) { sm[w] = s; sm[8 + w] = ss; }
    __syncthreads();
    if (t == 0) {
        float a = 0.f, c = 0.f;
        #pragma unroll
        for (int i = 0; i < 8; i++) { a += sm[i]; c += sm[8 + i]; }
        float mu  = a * (1.0f / DD);
        float var = c * (1.0f / DD) - mu * mu;
        s_mu = mu;
        s_r  = rsqrtf(var + 1e-5f);
    }
    __syncthreads();
    float mu = s_mu, r = s_r;
    float4 gv = ((const float4*)g)[t];
    float4 bv = ((const float4*)b)[t];
    float4 o;
    o.x = (v.x - mu) * r * gv.x + bv.x;
    o.y = (v.y - mu) * r * gv.y + bv.y;
    o.z = (v.z - mu) * r * gv.z + bv.z;
    o.w = (v.w - mu) * r * gv.w + bv.w;
    if (WRITE_LO) {
        uint32_t h01, h23, l01, l23;
        split2h(o.x, o.y, h01, l01);
        split2h(o.z, o.w, h23, l23);
        ((uint2*)(Yh + (size_t)row * DD))[t] = make_uint2(h01, h23);
        ((uint2*)(Yl + (size_t)row * DD))[t] = make_uint2(l01, l23);
    } else {
        ((uint2*)(Yh + (size_t)row * DD))[t] =
            make_uint2(pack2h(o.x, o.y), pack2h(o.z, o.w));
    }
}

// ================== weight prep ===============================================
__global__ void transpose_split_kernel(const float* __restrict__ W,
                                       __half* __restrict__ Wh,
                                       __half* __restrict__ Wl,
                                       int K, int N)
{
    __shared__ float t[32][33];
    int l = blockIdx.z;
    W  += (size_t)l * K * N;
    Wh += (size_t)l * N * K;
    Wl += (size_t)l * N * K;
    int n0 = blockIdx.x * 32, k0 = blockIdx.y * 32;
    int tx = threadIdx.x, ty = threadIdx.y;
    #pragma unroll
    for (int i = 0; i < 4; i++)
        t[ty + 8*i][tx] = W[(size_t)(k0 + ty + 8*i) * N + n0 + tx];
    __syncthreads();
    #pragma unroll
    for (int i = 0; i < 4; i++) {
        float v = t[tx][ty + 8*i];
        __half h = __float2half_rn(v);
        __half lo = __float2half_rn(v - __half2float(h));
        size_t oi = (size_t)(n0 + ty + 8*i) * K + k0 + tx;
        Wh[oi] = h; Wl[oi] = lo;
    }
}

__global__ void split_pair_kernel(const float* __restrict__ W,
                                  __half* __restrict__ Wh,
                                  __half* __restrict__ Wl)
{
    size_t i = (size_t)blockIdx.x * blockDim.x + threadIdx.x;
    float4 v = ((const float4*)W)[i];
    uint32_t h01, h23, l01, l23;
    split2h(v.x, v.y, h01, l01);
    split2h(v.z, v.w, h23, l23);
    ((uint2*)Wh)[i] = make_uint2(h01, h23);
    ((uint2*)Wl)[i] = make_uint2(l01, l23);
}

__global__ void tohalf_kernel(const float* __restrict__ W, __half* __restrict__ Wh)
{
    size_t i = (size_t)blockIdx.x * blockDim.x + threadIdx.x;
    float4 v = ((const float4*)W)[i];
    ((uint2*)Wh)[i] = make_uint2(pack2h(v.x, v.y), pack2h(v.z, v.w));
}

// ====================== HMMA fp16x2 GEMM =======================================
// C[M,N] = Ah[M,K](fp16) @ (Bh+Bl)^T[N,K], fp32 accum, 2-term product.
// 128x128 tile, K-step 64, 256 threads (8 warps, 4M x 2N).
// 2-stage, 2 CTAs/SM, SINGLE sync/iter: prefetch(t+1) issued before compute(t).
#define A_HI 0
#define B_HI 16384
#define B_LO 32768
#define STAGE_BYTES 49152
#define GEMM_DSMEM (2*STAGE_BYTES + 1024)

template<int RESMODE, bool OUTS>
__global__ void __launch_bounds__(256, 2)
gemm_hh(const __half* __restrict__ Ah,
        const __half* __restrict__ Bh, const __half* __restrict__ Bl,
        const float* __restrict__ bias,
        const float* __restrict__ resf,
        const __half* __restrict__ resh, const __half* __restrict__ resl,
        float* __restrict__ C,
        __half* __restrict__ Ch, __half* __restrict__ Cl,
        int M, int N, int K)
{
    extern __shared__ char dsm[];
    uint32_t raw = smem_u32(dsm);
    uint32_t tb = (raw + 1023u) & ~1023u;

    const int tid = threadIdx.x;
    const int l   = tid & 31;
    const int wid = tid >> 5;
    const int wm  = (wid & 3) * 32;
    const int wn  = (wid >> 2) * 64;
    const int bm  = blockIdx.x * 128;
    const int bn  = blockIdx.y * 128;

    const uint32_t hi16 = (uint32_t)((l >> 4) * 16);
    uint32_t abase[2], amask[2], bbase[4], bmask[4];
    #pragma unroll
    for (int mi = 0; mi < 2; mi++) {
        uint32_t r = (uint32_t)(wm + mi * 16 + (l & 15));
        abase[mi] = r * 128;
        amask[mi] = (r & 7) << 4;
    }
    #pragma unroll
    for (int nb = 0; nb < 4; nb++) {
        uint32_t r = (uint32_t)(wn + nb * 16 + (l & 15));
        bbase[nb] = r * 128;
        bmask[nb] = (r & 7) << 4;
    }

    float d[2][8][4];
    #pragma unroll
    for (int i = 0; i < 2; i++)
        #pragma unroll
        for (int j = 0; j < 8; j++)
            #pragma unroll
            for (int k = 0; k < 4; k++) d[i][j][k] = 0.f;

    const int nt = K >> 6;

    #define LOAD_T(stg, k0) { \
        uint32_t base = tb + (stg) * STAGE_BYTES; \
        _Pragma("unroll") \
        for (int i = 0; i < 4; i++) { \
            int c = tid + i * 256; int r = c >> 3, s = c & 7; \
            uint32_t off = sw128((uint32_t)(r * 128 + s * 16)); \
            size_t ga = (size_t)(bm + r) * K + (k0) + s * 8; \
            size_t gb = (size_t)(bn + r) * K + (k0) + s * 8; \
            cp16(base + A_HI + off, Ah + ga); \
            cp16(base + B_HI + off, Bh + gb); \
            cp16(base + B_LO + off, Bl + gb); } }

    LOAD_T(0, 0); CP_COMMIT();

    for (int t = 0; t < nt; t++) {
        CP_WAIT0();                 // stage t resident
        __syncthreads();            // all warps done with stage t-1
        if (t + 1 < nt) {
            LOAD_T((t + 1) & 1, (t + 1) << 6);   // overwrite buf of t-1 (consumed)
            CP_COMMIT();
        }
        {
            uint32_t sb = tb + (uint32_t)(t & 1) * STAGE_BYTES;
            #pragma unroll
            for (int ks = 0; ks < 4; ks++) {
                const uint32_t ko = (uint32_t)(ks * 32);
                uint32_t aH[2][4];
                #pragma unroll
                for (int mi = 0; mi < 2; mi++) {
                    uint32_t ao = abase[mi] + ((hi16 + ko) ^ amask[mi]);
                    ldsm_x4(aH[mi], sb + A_HI + ao);
                }
                uint32_t bH[8][2], bL[8][2];
                #pragma unroll
                for (int nb = 0; nb < 4; nb++) {
                    uint32_t bo = bbase[nb] + ((hi16 + ko) ^ bmask[nb]);
                    uint32_t r4[4];
                    ldsm_x4(r4, sb + B_HI + bo);
                    bH[2*nb][0] = r4[0]; bH[2*nb][1] = r4[2];
                    bH[2*nb+1][0] = r4[1]; bH[2*nb+1][1] = r4[3];
                    ldsm_x4(r4, sb + B_LO + bo);
                    bL[2*nb][0] = r4[0]; bL[2*nb][1] = r4[2];
                    bL[2*nb+1][0] = r4[1]; bL[2*nb+1][1] = r4[3];
                }
                #pragma unroll
                for (int nj = 0; nj < 8; nj++) {
                    #pragma unroll
                    for (int mi = 0; mi < 2; mi++) {
                        mma_f16(d[mi][nj], aH[mi], bH[nj]);
                        mma_f16(d[mi][nj], aH[mi], bL[nj]);
                    }
                }
            }
        }
    }

    // ---- epilogue ----
    #pragma unroll
    for (int mi = 0; mi < 2; mi++) {
        #pragma unroll
        for (int half = 0; half < 2; half++) {
            int row = bm + wm + mi * 16 + half * 8 + (l >> 2);
            #pragma unroll
            for (int nj = 0; nj < 8; nj++) {
                int col = bn + wn + nj * 8 + 2 * (l & 3);
                float v0 = d[mi][nj][2 * half];
                float v1 = d[mi][nj][2 * half + 1];
                if (bias) { v0 += bias[col]; v1 += bias[col + 1]; }
                size_t ri = (size_t)row * N + col;
                if (RESMODE == 1) {
                    float2 r2 = *(const float2*)&resf[ri];
                    v0 += r2.x; v1 += r2.y;
                } else if (RESMODE == 2) {
                    uint32_t rh = *(const uint32_t*)&resh[ri];
                    uint32_t rl = *(const uint32_t*)&resl[ri];
                    v0 += h2sum(rh, rl, 0);
                    v1 += h2sum(rh, rl, 1);
                }
                if (OUTS) {
                    uint32_t hi, lo;
                    split2h(v0, v1, hi, lo);
                    *(uint32_t*)&Ch[ri] = hi;
                    *(uint32_t*)&Cl[ri] = lo;
                } else {
                    float2 o; o.x = v0; o.y = v1;
                    *(float2*)&C[ri] = o;
                }
            }
        }
    }
}

// ================== HMMA flash attention (fp16x2) ==============================
// Q hi only; K,V hi/lo pairs. 2 CTAs/SM.
// Single sync/iter: prefetch(t+1) issued before compute(t).
#define AQ_HI 0
#define AKV_OFF 16384
#define AKV_BUF 32768           // [Kh 8K][Kl 8K][Vh 8K][Vl 8K]
#define ATTN_DSMEM (AKV_OFF + 2*AKV_BUF + 1024)

__global__ void __launch_bounds__(256, 2)
attn_mma(const __half* __restrict__ qh, const __half* __restrict__ ql,
         __half* __restrict__ oh)
{
    extern __shared__ char dsm[];
    uint32_t raw = smem_u32(dsm);
    uint32_t tb = (raw + 1023u) & ~1023u;

    const int tid = threadIdx.x;
    const int l   = tid & 31;
    const int w   = tid >> 5;
    const int bh  = blockIdx.y;
    const int b   = bh >> 4;
    const int h   = bh & 15;
    const int q0  = blockIdx.x * 128;
    const size_t hoff = (size_t)h * DH;

    #pragma unroll
    for (int i = 0; i < 4; i++) {
        int lin = tid + i * 256;
        int row = lin >> 3, ch = lin & 7;
        const __half* src = qh + (size_t)(b * SS + q0 + row) * (3 * DD) + hoff + ch * 8;
        cp16(tb + AQ_HI + sw128((uint32_t)(row * 128 + ch * 16)), src);
    }
    #define LOAD_KV(t, buf) { \
        _Pragma("unroll") \
        for (int i = 0; i < 8; i++) { \
            int lin = tid + i * 256; \
            int kv = lin >> 10, reg = (lin >> 9) & 1, row = (lin >> 3) & 63, ch = lin & 7; \
            const __half* src = (reg ? ql : qh) \
                + (size_t)(b * SS + (t) * 64 + row) * (3 * DD) \
                + (kv ? 2 * DD : DD) + hoff + ch * 8; \
            cp16(tb + AKV_OFF + (buf) * AKV_BUF + kv * 16384 + reg * 8192 \
                 + sw128((uint32_t)(row * 128 + ch * 16)), src); } }

    LOAD_KV(0, 0); CP_COMMIT();

    float od[8][4];
    #pragma unroll
    for (int j = 0; j < 8; j++)
        #pragma unroll
        for (int k = 0; k < 4; k++) od[j][k] = 0.f;
    float m0 = -1e30f, m1 = -1e30f, l0 = 0.f, l1 = 0.f;

    uint32_t aQh[4][4];
    const uint32_t qrow = (uint32_t)(w * 16 + (l & 15));
    const uint32_t qmask = (qrow & 7) << 4;
    const uint32_t hi16 = (uint32_t)((l >> 4) * 16);

    for (int t = 0; t < 16; t++) {
        const int buf = t & 1;
        CP_WAIT0();                 // tile t (and Q on t=0) resident
        __syncthreads();            // all warps done with tile t-1
        if (t + 1 < 16) { LOAD_KV(t + 1, buf ^ 1); CP_COMMIT(); }
        if (t == 0) {
            #pragma unroll
            for (int ks = 0; ks < 4; ks++) {
                uint32_t off = qrow * 128 + ((hi16 + ks * 32) ^ qmask);
                ldsm_x4(aQh[ks], tb + AQ_HI + off);
            }
        }
        const uint32_t sK = tb + AKV_OFF + buf * AKV_BUF;
        const uint32_t sKl = sK + 8192;
        const uint32_t sV = sK + 16384;
        const uint32_t sVl = sK + 24576;

        float sc[8][4];
        #pragma unroll
        for (int j = 0; j < 8; j++)
            #pragma unroll
            for (int k = 0; k < 4; k++) sc[j][k] = 0.f;
        #pragma unroll
        for (int ks = 0; ks < 4; ks++) {
            uint32_t bKh[8][2], bKl[8][2];
            #pragma unroll
            for (int nb = 0; nb < 4; nb++) {
                uint32_t row = (uint32_t)(nb * 16 + (l & 15));
                uint32_t off = row * 128 + ((hi16 + ks * 32) ^ ((row & 7) << 4));
                uint32_t r4[4];
                ldsm_x4(r4, sK + off);
                bKh[2*nb][0] = r4[0]; bKh[2*nb][1] = r4[2];
                bKh[2*nb+1][0] = r4[1]; bKh[2*nb+1][1] = r4[3];
                ldsm_x4(r4, sKl + off);
                bKl[2*nb][0] = r4[0]; bKl[2*nb][1] = r4[2];
                bKl[2*nb+1][0] = r4[1]; bKl[2*nb+1][1] = r4[3];
            }
            #pragma unroll
            for (int nj = 0; nj < 8; nj++) {
                mma_f16(sc[nj], aQh[ks], bKh[nj]);
                mma_f16(sc[nj], aQh[ks], bKl[nj]);
            }
        }

        float nm0 = m0, nm1 = m1;
        #pragma unroll
        for (int nj = 0; nj < 8; nj++) {
            nm0 = fmaxf(nm0, fmaxf(sc[nj][0], sc[nj][1]));
            nm1 = fmaxf(nm1, fmaxf(sc[nj][2], sc[nj][3]));
        }
        nm0 = fmaxf(nm0, __shfl_xor_sync(0xFFFFFFFFu, nm0, 1));
        nm0 = fmaxf(nm0, __shfl_xor_sync(0xFFFFFFFFu, nm0, 2));
        nm1 = fmaxf(nm1, __shfl_xor_sync(0xFFFFFFFFu, nm1, 1));
        nm1 = fmaxf(nm1, __shfl_xor_sync(0xFFFFFFFFu, nm1, 2));
        float cor0 = __expf(m0 - nm0), cor1 = __expf(m1 - nm1);
        m0 = nm0; m1 = nm1;
        float rs0 = 0.f, rs1 = 0.f;
        #pragma unroll
        for (int nj = 0; nj < 8; nj++) {
            sc[nj][0] = __expf(sc[nj][0] - nm0);
            sc[nj][1] = __expf(sc[nj][1] - nm0);
            sc[nj][2] = __expf(sc[nj][2] - nm1);
            sc[nj][3] = __expf(sc[nj][3] - nm1);
            rs0 += sc[nj][0] + sc[nj][1];
            rs1 += sc[nj][2] + sc[nj][3];
        }
        rs0 += __shfl_xor_sync(0xFFFFFFFFu, rs0, 1);
        rs0 += __shfl_xor_sync(0xFFFFFFFFu, rs0, 2);
        rs1 += __shfl_xor_sync(0xFFFFFFFFu, rs1, 1);
        rs1 += __shfl_xor_sync(0xFFFFFFFFu, rs1, 2);
        l0 = l0 * cor0 + rs0;
        l1 = l1 * cor1 + rs1;
        #pragma unroll
        for (int nj = 0; nj < 8; nj++) {
            od[nj][0] *= cor0; od[nj][1] *= cor0;
            od[nj][2] *= cor1; od[nj][3] *= cor1;
        }

        #pragma unroll
        for (int kj = 0; kj < 4; kj++) {
            uint32_t aPh[4];
            aPh[0] = pack2h(sc[2*kj][0],   sc[2*kj][1]);
            aPh[1] = pack2h(sc[2*kj][2],   sc[2*kj][3]);
            aPh[2] = pack2h(sc[2*kj+1][0], sc[2*kj+1][1]);
            aPh[3] = pack2h(sc[2*kj+1][2], sc[2*kj+1][3]);
            const uint32_t mat = (uint32_t)(l >> 3);
            const uint32_t vrow = (uint32_t)(kj * 16 + (mat & 1) * 8 + (l & 7));
            const uint32_t vmask = (vrow & 7) << 4;
            #pragma unroll
            for (int pp = 0; pp < 4; pp++) {
                uint32_t off = vrow * 128 + (((uint32_t)(pp * 32) + (mat >> 1) * 16) ^ vmask);
                uint32_t rh[4], rl[4];
                ldsm_x4_t(rh, sV + off);
                ldsm_x4_t(rl, sVl + off);
                uint32_t b0h[2] = {rh[0], rh[1]}, b1h[2] = {rh[2], rh[3]};
                uint32_t b0l[2] = {rl[0], rl[1]}, b1l[2] = {rl[2], rl[3]};
                mma_f16(od[2*pp],   aPh, b0h);
                mma_f16(od[2*pp],   aPh, b0l);
                mma_f16(od[2*pp+1], aPh, b1h);
                mma_f16(od[2*pp+1], aPh, b1l);
            }
        }
    }

    float inv0 = 1.0f / l0, inv1 = 1.0f / l1;
    int row0 = q0 + w * 16 + (l >> 2);
    #pragma unroll
    for (int nj = 0; nj < 8; nj++) {
        int col = (int)hoff + nj * 8 + 2 * (l & 3);
        size_t ri0 = (size_t)(b * SS + row0) * DD + col;
        size_t ri1 = (size_t)(b * SS + row0 + 8) * DD + col;
        *(uint32_t*)&oh[ri0] = pack2h(od[nj][0] * inv0, od[nj][1] * inv0);
        *(uint32_t*)&oh[ri1] = pack2h(od[nj][2] * inv1, od[nj][3] * inv1);
    }
}

// ---------------- launch -------------------------------------------------------
extern "C" void kernel_launch(void* const* d_in, const int* in_sizes, int n_in,
                              void* d_out, int out_size)
{
    const int*   X     = (const int*)  d_in[0];
    const float* emb   = (const float*)d_in[1];
    const float* pe    = (const float*)d_in[2];
    const float* ln1_g = (const float*)d_in[3];
    const float* ln1_b = (const float*)d_in[4];
    const float* wa    = (const float*)d_in[5];
    const float* ba    = (const float*)d_in[6];
    const float* wp    = (const float*)d_in[7];
    const float* bp    = (const float*)d_in[8];
    const float* ln2_g = (const float*)d_in[9];
    const float* ln2_b = (const float*)d_in[10];
    const float* wf    = (const float*)d_in[11];
    const float* bf    = (const float*)d_in[12];
    const float* wout  = (const float*)d_in[13];
    float* logits = (float*)d_out;

    float *x;
    __half *wh, *wl, *qkvh, *qkvl, *hh, *hl, *th, *ah, *xh;
    cudaGetSymbolAddress((void**)&x,    g_x);
    cudaGetSymbolAddress((void**)&wh,   g_wh);
    cudaGetSymbolAddress((void**)&wl,   g_wl);
    cudaGetSymbolAddress((void**)&qkvh, g_qkvh);
    cudaGetSymbolAddress((void**)&qkvl, g_qkvl);
    cudaGetSymbolAddress((void**)&hh,   g_hh);
    cudaGetSymbolAddress((void**)&hl,   g_hl);
    cudaGetSymbolAddress((void**)&th,   g_th);
    cudaGetSymbolAddress((void**)&ah,   g_ah);
    cudaGetSymbolAddress((void**)&xh,   g_xh);

    cudaFuncSetAttribute(gemm_hh<0,true>,  cudaFuncAttributeMaxDynamicSharedMemorySize, GEMM_DSMEM);
    cudaFuncSetAttribute(gemm_hh<2,false>, cudaFuncAttributeMaxDynamicSharedMemorySize, GEMM_DSMEM);
    cudaFuncSetAttribute(gemm_hh<1,false>, cudaFuncAttributeMaxDynamicSharedMemorySize, GEMM_DSMEM);
    cudaFuncSetAttribute(gemm_hh<0,false>, cudaFuncAttributeMaxDynamicSharedMemorySize, GEMM_DSMEM);
    cudaFuncSetAttribute(attn_mma, cudaFuncAttributeMaxDynamicSharedMemorySize, ATTN_DSMEM);

    // weight prep (per replay, HBM-stream bound)
    transpose_split_kernel<<<dim3(3*DD/32, DD/32, LL), dim3(32,8)>>>(
        wa, wh + WA_T_OFF, wl + WA_T_OFF, DD, 3*DD);
    transpose_split_kernel<<<dim3(DD/32, DD/32, LL), dim3(32,8)>>>(
        wp, wh + WP_T_OFF, wl + WP_T_OFF, DD, DD);
    transpose_split_kernel<<<dim3(DD/32, DD/32, LL), dim3(32,8)>>>(
        wf, wh + WF_T_OFF, wl + WF_T_OFF, DD, DD);
    split_pair_kernel<<<(VV*1024/4)/256, 256>>>(wout, wh + WOUT_OFF, wl + WOUT_OFF);

    embed_kernel<<<NTOK, 256>>>(X, emb, pe, x);

    for (int i = 0; i < LL; i++) {
        const float* ba_i = ba + (size_t)i * 3 * DD;
        const float* bp_i = bp + (size_t)i * DD;
        const float* bf_i = bf + (size_t)i * DD;
        const __half* wa_h = wh + WA_T_OFF + (size_t)i * 3*DD * DD;
        const __half* wa_l = wl + WA_T_OFF + (size_t)i * 3*DD * DD;
        const __half* wp_h = wh + WP_T_OFF + (size_t)i * DD * DD;
        const __half* wp_l = wl + WP_T_OFF + (size_t)i * DD * DD;
        const __half* wf_h = wh + WF_T_OFF + (size_t)i * DD * DD;
        const __half* wf_l = wl + WF_T_OFF + (size_t)i * DD * DD;

        ln_h_kernel<true><<<NTOK, 256>>>(x, ln1_g + (size_t)i * DD, ln1_b + (size_t)i * DD, hh, hl);
        gemm_hh<0,true><<<dim3(NTOK/128, 3*DD/128), 256, GEMM_DSMEM>>>(
            hh, wa_h, wa_l, ba_i, nullptr, nullptr, nullptr,
            nullptr, qkvh, qkvl, NTOK, 3*DD, DD);
        attn_mma<<<dim3(SS/128, BB*HH), 256, ATTN_DSMEM>>>(qkvh, qkvl, ah);
        gemm_hh<2,false><<<dim3(NTOK/128, DD/128), 256, GEMM_DSMEM>>>(
            ah, wp_h, wp_l, bp_i, nullptr, hh, hl,
            x, nullptr, nullptr, NTOK, DD, DD);
        ln_h_kernel<false><<<NTOK, 256>>>(x, ln2_g + (size_t)i * DD, ln2_b + (size_t)i * DD, th, nullptr);
        gemm_hh<1,false><<<dim3(NTOK/128, DD/128), 256, GEMM_DSMEM>>>(
            th, wf_h, wf_l, bf_i, x, nullptr, nullptr,
            x, nullptr, nullptr, NTOK, DD, DD);
    }

    tohalf_kernel<<<(NTOK*DD/4)/256, 256>>>(x, xh);
    gemm_hh<0,false><<<dim3(NTOK/128, VV/128), 256, GEMM_DSMEM>>>(
        xh, wh + WOUT_OFF, wl + WOUT_OFF, nullptr, nullptr, nullptr, nullptr,
        logits, nullptr, nullptr, NTOK, VV, DD);
    (void)in_sizes; (void)n_in; (void)out_size;
}